// round 12
// baseline (speedup 1.0000x reference)
#include <cuda_runtime.h>
#include <math.h>

// dims
#define BB   2
#define NNODE 256
#define DNv  128
#define DEv  64
#define DHv  128
#define Hh   8
#define DHHv 16
#define DNHv 512
#define DEHv 256
#define NLAYER 2
#define ATT_SCALE 0.088388347648318447f  // 1/sqrt(128)

typedef unsigned long long u64t;

// packed fp32x2 FMA (Blackwell): one issue slot, two fp32 FMAs, exact .rn numerics
__device__ __forceinline__ void ffma2(u64t& acc, u64t a, u64t b) {
    asm("fma.rn.f32x2 %0, %1, %2, %0;" : "+l"(acc) : "l"(a), "l"(b));
}
__device__ __forceinline__ u64t pack_ww(float w) {
    u64t r; asm("mov.b64 %0, {%1, %1};" : "=l"(r) : "f"(w)); return r;
}
union F4u { float4 v; u64t p[2]; float f[4]; };
union U2u { u64t p; float f[2]; };

// ---------------- scratch (device globals; no allocations allowed) ----------
__device__ float g_x[BB*NNODE*DNv];
__device__ float g_ebuf[BB*NNODE*NNODE*DEv];   // intermediate e (after layer 0)
__device__ float g_qkvn[BB*NNODE*3*DHv];
__device__ float g_attnout[BB*NNODE*DHv];
__device__ float g_src[BB*NNODE*DEHv];
__device__ float g_tgt[BB*NNODE*DEHv];

__device__ __forceinline__ float gelu_f(float x) {
    return 0.5f * x * (1.0f + erff(x * 0.70710678118654752440f));
}

// ---------------- copy in: node features only --------------------------------
__global__ void k_copy_in(const float4* __restrict__ node) {
    int tid = blockIdx.x * blockDim.x + threadIdx.x;
    float4* x4 = (float4*)g_x;
    if (tid < BB*NNODE*DNv/4) x4[tid] = node[tid];
}

// ---------------- qkv_n for layer 0 only -------------------------------------
__global__ void k_qkvn(const float* __restrict__ W) {  // W: [128][384]
    __shared__ float sx[DNv];
    int row = blockIdx.x;
    int t = threadIdx.x;   // 128 threads
    sx[t] = g_x[row*DNv + t];
    __syncthreads();
    for (int c = t; c < 3*DHv; c += 128) {
        float acc = 0.f;
        #pragma unroll 16
        for (int k = 0; k < DNv; k++) acc += sx[k] * __ldg(&W[k*384 + c]);
        g_qkvn[row*384 + c] = acc;
    }
}

// ---------------- fused attention: per (b,i), flash-style over j -------------
// ev-contracted E-GEMM (eq,ek,em logical cols). SMEM diet for occ 3:
//   sE holds only eq,ek (stride 257, conflict-free);
//   em is multiplied by vn at GEMM write-time into compact sVM;
//   kn loaded via LDG.128 directly in the dot loop (no skn tile).
#define SE2 257
#define VM_STR 132
#define SMEM_ATTN ((32*SE2 + 64*36 + 32*VM_STR + 128 + 8*65 + 8*36) * 4)
__global__ void __launch_bounds__(256, 3) k_attn(const float* __restrict__ We,
                                                 const float* __restrict__ eread) {
    extern __shared__ float sm[];
    float* sE  = sm;                   // eq/ek tile [32][257]
    float* seT = sE  + 32*SE2;         // e tile transposed [k=64][jj], stride 36
    float* sVM = seT + 64*36;          // vn*em tile [32][132]
    float* sq  = sVM + 32*VM_STR;      // q row (128)
    float* sf  = sq + 128;             // f per head [8][65]
    float* sp  = sf + 8*65;            // p per head [8][36]

    int b = blockIdx.x / NNODE, i = blockIdx.x % NNODE;
    int t = threadIdx.x, lane = t & 31;
    int h = t >> 5;  // 8 warps = 8 heads
    int dd = lane & 15, hi = lane >> 4;
    int bN = b*NNODE;

    // E-GEMM worker mapping: rows rh*16..+15, logical cols cb, cb+128, cb+256
    int rh = t >> 7, cb = t & 127;
    int acx0, acx1, acx2;       // actual weight cols
    int sidx0, sidx1, sidx2;    // dest index within row (sE or sVM)
    int ty0, ty1, ty2;          // 0 -> sE (eq/ek), 1 -> sVM (em*vn)
    int vo0, vo1, vo2;          // vn offset within qkvn row (em only)
    {
        int L0 = cb, L1 = cb + 128, L2 = cb + 256;
        int w0 = L0 % 48, w1 = L1 % 48, w2 = L2 % 48;
        int h0 = L0 / 48, h1 = L1 / 48, h2 = L2 / 48;
        acx0 = h0*64 + (w0 < 32 ? w0 : w0 + 16);
        acx1 = h1*64 + (w1 < 32 ? w1 : w1 + 16);
        acx2 = h2*64 + (w2 < 32 ? w2 : w2 + 16);
        ty0 = (w0 >= 32); sidx0 = ty0 ? h0*16 + (w0-32) : h0*32 + w0; vo0 = h0*48 + 16 + w0;
        ty1 = (w1 >= 32); sidx1 = ty1 ? h1*16 + (w1-32) : h1*32 + w1; vo1 = h1*48 + 16 + w1;
        ty2 = (w2 >= 32); sidx2 = ty2 ? h2*16 + (w2-32) : h2*32 + w2; vo2 = h2*48 + 16 + w2;
        // for em: vn offset = h*48 + 32 + d = h*48 + 16 + w (since w = 16 + ... wait w>=32: h*48+32+(w-32) = h*48+w) 
    }
    // NOTE: vn offset for em col = h*48 + 32 + (w-32) = h*48 + w
    {
        int L0 = cb, L1 = cb + 128, L2 = cb + 256;
        vo0 = (L0/48)*48 + (L0%48);
        vo1 = (L1/48)*48 + (L1%48);
        vo2 = (L2/48)*48 + (L2%48);
        // em logical position within qkvn row: h*48 + w  (w in 32..47 -> vn slot)
    }

    if (t < DHv) { int hh = t >> 4, d = t & 15; sq[t] = g_qkvn[(bN + i)*384 + hh*48 + d]; }

    float m = -3.4e38f, lsum = 0.f, o = 0.f;
    float f0 = 0.f, f1 = 0.f;           // f cols: lane, lane+32
    const float* erow = eread + (size_t)(bN + i) * NNODE * DEv;

    for (int j0 = 0; j0 < NNODE; j0 += 32) {
        __syncthreads();  // protect smem reuse from previous tile
        // load e tile transposed
        for (int idx = t; idx < 32*64; idx += 256) {
            int jj = idx >> 6, c = idx & 63;
            seT[c*36 + jj] = erow[(j0 + jj)*DEv + c];
        }
        __syncthreads();
        // E = e_tile @ Wqkv_e[eq,ek,em] (32 x 384): 256 threads, 3 cols x 16 rows
        {
            u64t a0[8], a1[8], a2[8];
            #pragma unroll
            for (int q = 0; q < 8; q++) { a0[q] = 0ull; a1[q] = 0ull; a2[q] = 0ull; }
            #pragma unroll 4
            for (int k = 0; k < 64; k++) {
                u64t w0 = pack_ww(__ldg(&We[k*512 + acx0]));
                u64t w1 = pack_ww(__ldg(&We[k*512 + acx1]));
                u64t w2 = pack_ww(__ldg(&We[k*512 + acx2]));
                const float4* e4 = (const float4*)(seT + k*36 + rh*16);
                #pragma unroll
                for (int q4 = 0; q4 < 4; q4++) {
                    F4u ev; ev.v = e4[q4];
                    ffma2(a0[q4*2],   ev.p[0], w0);
                    ffma2(a0[q4*2+1], ev.p[1], w0);
                    ffma2(a1[q4*2],   ev.p[0], w1);
                    ffma2(a1[q4*2+1], ev.p[1], w1);
                    ffma2(a2[q4*2],   ev.p[0], w2);
                    ffma2(a2[q4*2+1], ev.p[1], w2);
                }
            }
            #pragma unroll
            for (int q = 0; q < 8; q++) {
                int row = rh*16 + 2*q;
                size_t r0 = (size_t)(bN + j0 + row)*384;
                size_t r1 = (size_t)(bN + j0 + row + 1)*384;
                U2u u0; u0.p = a0[q];
                if (ty0) {
                    sVM[row*VM_STR + sidx0]     = u0.f[0] * __ldg(&g_qkvn[r0 + vo0]);
                    sVM[(row+1)*VM_STR + sidx0] = u0.f[1] * __ldg(&g_qkvn[r1 + vo0]);
                } else {
                    sE[row*SE2 + sidx0]     = u0.f[0];
                    sE[(row+1)*SE2 + sidx0] = u0.f[1];
                }
                U2u u1; u1.p = a1[q];
                if (ty1) {
                    sVM[row*VM_STR + sidx1]     = u1.f[0] * __ldg(&g_qkvn[r0 + vo1]);
                    sVM[(row+1)*VM_STR + sidx1] = u1.f[1] * __ldg(&g_qkvn[r1 + vo1]);
                } else {
                    sE[row*SE2 + sidx1]     = u1.f[0];
                    sE[(row+1)*SE2 + sidx1] = u1.f[1];
                }
                U2u u2; u2.p = a2[q];
                if (ty2) {
                    sVM[row*VM_STR + sidx2]     = u2.f[0] * __ldg(&g_qkvn[r0 + vo2]);
                    sVM[(row+1)*VM_STR + sidx2] = u2.f[1] * __ldg(&g_qkvn[r1 + vo2]);
                } else {
                    sE[row*SE2 + sidx2]     = u2.f[0];
                    sE[(row+1)*SE2 + sidx2] = u2.f[1];
                }
            }
        }
        __syncthreads();
        // dots (lane = j within tile): kn loaded directly via LDG.128
        const float* Er = sE + lane*SE2 + h*32;
        F4u kn4[4];
        {
            const float4* knp = (const float4*)(g_qkvn + (size_t)(bN + j0 + lane)*384 + h*48 + 16);
            #pragma unroll
            for (int u = 0; u < 4; u++) kn4[u].v = __ldg(&knp[u]);
        }
        float dot = 0.f;
        #pragma unroll
        for (int d = 0; d < 16; d++)
            dot += (sq[h*16 + d] + Er[d]) * (kn4[d >> 2].f[d & 3] + Er[16 + d]);
        dot *= ATT_SCALE;
        float mt = dot;
        #pragma unroll
        for (int off = 16; off; off >>= 1) mt = fmaxf(mt, __shfl_xor_sync(0xffffffffu, mt, off));
        float mnew = fmaxf(m, mt);
        float p = expf(dot - mnew);
        float corr = expf(m - mnew);   // first tile: exp(-huge) = 0
        float ps = p;
        #pragma unroll
        for (int off = 16; off; off >>= 1) ps += __shfl_xor_sync(0xffffffffu, ps, off);
        lsum = lsum * corr + ps;
        o *= corr; f0 *= corr; f1 *= corr;
        // stage p for this warp's tile (own row; syncwarp is enough)
        sp[h*36 + lane] = p;
        __syncwarp();
        // f accumulation, float4 over j (seT rows are j-contiguous)
        {
            const float4* pv4 = (const float4*)(sp + h*36);
            const float4* e0v = (const float4*)(seT + lane*36);
            const float4* e1v = (const float4*)(seT + (lane + 32)*36);
            #pragma unroll
            for (int jq = 0; jq < 8; jq++) {
                float4 pv = pv4[jq];
                float4 a = e0v[jq], bq = e1v[jq];
                f0 += pv.x*a.x + pv.y*a.y + pv.z*a.z + pv.w*a.w;
                f1 += pv.x*bq.x + pv.y*bq.y + pv.z*bq.z + pv.w*bq.w;
            }
        }
        // o[d] += sum_j p_j * (vn*em)[j,d] — j split by lane-half
        #pragma unroll
        for (int jj = 0; jj < 16; jj++) {
            int jjj = hi*16 + jj;
            float pj = __shfl_sync(0xffffffffu, p, jjj);
            o += pj * sVM[jjj*VM_STR + h*16 + dd];
        }
        m = mnew;
    }
    // combine the two j-halves of o
    float of = o + __shfl_xor_sync(0xffffffffu, o, 16);
    // stash f for this head, then apply Wev projection (exact linear reorder)
    sf[h*65 + lane] = f0;
    sf[h*65 + 32 + lane] = f1;
    __syncwarp();
    if (lane < 16) {
        float fv = 0.f;
        #pragma unroll 8
        for (int c = 0; c < 64; c++)
            fv += sf[h*65 + c] * __ldg(&We[c*512 + h*64 + 32 + lane]);
        g_attnout[(bN + i)*DHv + h*16 + lane] = (of + fv) / lsum;
    }
}

// ---------------- LayerNorm helper for 128-wide rows (128 threads) -----------
__device__ __forceinline__ float ln128(float r, const float* __restrict__ g,
                                       const float* __restrict__ bta, float* sred, int t) {
    __syncthreads();  // protect sred reuse
    int warp = t >> 5, lane = t & 31;
    float s = r, ss = r*r;
    #pragma unroll
    for (int off = 16; off; off >>= 1) {
        s  += __shfl_xor_sync(0xffffffffu, s, off);
        ss += __shfl_xor_sync(0xffffffffu, ss, off);
    }
    if (lane == 0) { sred[warp] = s; sred[4 + warp] = ss; }
    __syncthreads();
    if (t == 0) {
        float S = sred[0]+sred[1]+sred[2]+sred[3];
        float SS = sred[4]+sred[5]+sred[6]+sred[7];
        float mean = S * (1.f/128.f);
        float var = SS * (1.f/128.f) - mean*mean;
        sred[8] = mean;
        sred[9] = rsqrtf(var + 1e-5f);
    }
    __syncthreads();
    return (r - sred[8]) * sred[9] * g[t] + bta[t];
}

// ---------------- node update 1: x = ln(x + (attn@Wo+bo)@Wl0 + bl0) ----------
__global__ void k_node1(const float* __restrict__ Wo, const float* __restrict__ bo,
                        const float* __restrict__ Wl0, const float* __restrict__ bl0,
                        const float* __restrict__ gam, const float* __restrict__ bet) {
    __shared__ float sa[DHv];
    __shared__ float st[DNv];
    __shared__ float sred[10];
    int row = blockIdx.x; int t = threadIdx.x;
    sa[t] = g_attnout[row*DHv + t];
    __syncthreads();
    float acc = bo[t];
    #pragma unroll 16
    for (int k = 0; k < DHv; k++) acc += sa[k] * __ldg(&Wo[k*DNv + t]);
    st[t] = acc;
    __syncthreads();
    float u = bl0[t];
    #pragma unroll 16
    for (int k = 0; k < DNv; k++) u += st[k] * __ldg(&Wl0[k*DNv + t]);
    float r = g_x[row*DNv + t] + u;
    g_x[row*DNv + t] = ln128(r, gam, bet, sred, t);
}

// ---------------- node MLP: x = ln(x + gelu(x@Wm1)@Wm2 + bm2) ----------------
// wout: also write final x into xout (d_out) on the last layer
__global__ void k_node2(const float* __restrict__ Wm1, const float* __restrict__ Wm2,
                        const float* __restrict__ bm2,
                        const float* __restrict__ gam, const float* __restrict__ bet,
                        float* __restrict__ xout, int wout) {
    __shared__ float sx[DNv];
    __shared__ float sh[DNHv];
    __shared__ float sred[10];
    int row = blockIdx.x; int t = threadIdx.x;
    float xv = g_x[row*DNv + t];
    sx[t] = xv;
    __syncthreads();
    for (int c = t; c < DNHv; c += 128) {
        float acc = 0.f;
        #pragma unroll 16
        for (int k = 0; k < DNv; k++) acc += sx[k] * __ldg(&Wm1[k*DNHv + c]);
        sh[c] = gelu_f(acc);
    }
    __syncthreads();
    float u = bm2[t];
    #pragma unroll 16
    for (int k = 0; k < DNHv; k++) u += sh[k] * __ldg(&Wm2[k*DNv + t]);
    float r = xv + u;
    float y = ln128(r, gam, bet, sred, t);
    g_x[row*DNv + t] = y;
    if (wout) xout[row*DNv + t] = y;
}

// ---------------- aux: srctgt (blocks 0..511) + next-layer qkvn (512..1023) --
__global__ void k_aux(const float* __restrict__ Ws, const float* __restrict__ bs,
                      const float* __restrict__ Wt, const float* __restrict__ bt,
                      const float* __restrict__ Wqn, int do_qkv) {
    __shared__ float sx[DNv];
    int t = threadIdx.x;  // 256 threads
    if (blockIdx.x < BB*NNODE) {
        int row = blockIdx.x;
        if (t < DNv) sx[t] = g_x[row*DNv + t];
        __syncthreads();
        float a = bs[t], c2 = bt[t];
        #pragma unroll 16
        for (int k = 0; k < DNv; k++) {
            float xv = sx[k];
            a  += xv * __ldg(&Ws[k*DEHv + t]);
            c2 += xv * __ldg(&Wt[k*DEHv + t]);
        }
        g_src[row*DEHv + t] = a;
        g_tgt[row*DEHv + t] = c2;
    } else {
        if (!do_qkv) return;
        int row = blockIdx.x - BB*NNODE;
        if (t < DNv) sx[t] = g_x[row*DNv + t];
        __syncthreads();
        for (int c = t; c < 3*DHv; c += 256) {
            float acc = 0.f;
            #pragma unroll 16
            for (int k = 0; k < DNv; k++) acc += sx[k] * __ldg(&Wqn[k*384 + c]);
            g_qkvn[row*384 + c] = acc;
        }
    }
}

// ---------------- fused edge update kernel -----------------------------------
// block = (b, i, j-tile of 32), 256 threads.  r2 aliases stT (disjoint lifetimes)
#define SMEM_EDGE ((128*36 + 256*36 + 2048 + 64*36 + 256) * 4)
__global__ void __launch_bounds__(256, 3) k_edge(
                       const float* __restrict__ We0, const float* __restrict__ be0,
                       const float* __restrict__ We1, const float* __restrict__ be1,
                       const float* __restrict__ g0, const float* __restrict__ b0,
                       const float* __restrict__ Wem1, const float* __restrict__ Wem2,
                       const float* __restrict__ bem2,
                       const float* __restrict__ g1, const float* __restrict__ b1,
                       const float* __restrict__ eread, float* __restrict__ ewrite) {
    extern __shared__ float sm[];
    float* secatT = sm;                 // [k=128][jj=32] stride 36
    float* shT    = secatT + 128*36;    // [k=256][jj=32] stride 36
    float* stRM   = shT + 256*36;       // [jj=32][c=64] row-major
    float* stT    = stRM + 2048;        // [k=64][jj=32] stride 36
    float* r2     = stT;                // ALIAS: r2 live only after stT is dead
    float* ssrc   = stT + 64*36;        // 256

    int jt = blockIdx.x & 7;
    int bi = blockIdx.x >> 3;           // b*N+i
    int b = bi >> 8, i = bi & 255;
    int j0 = jt * 32;
    int t = threadIdx.x;

    // load ecat = [e_ij, e_ji] transposed
    for (int idx = t; idx < 32*64; idx += 256) {
        int jj = idx >> 6, c = idx & 63;
        secatT[c*36 + jj]        = eread[((size_t)bi*NNODE + j0 + jj)*DEv + c];
        secatT[(64 + c)*36 + jj] = eread[((size_t)(b*NNODE + j0 + jj)*NNODE + i)*DEv + c];
    }
    ssrc[t] = g_src[(size_t)bi*DEHv + t];
    __syncthreads();

    // h = gelu(ecat @ We0 + be0 + src_i + tgt_j)   (32 x 256), C=2 cols x 16 rows
    {
        int c = t & 127;     // cols c and c+128
        int jg = t >> 7;     // row-half: rows jg*16 .. jg*16+15
        u64t acc0[8], acc1[8];
        u64t init0 = pack_ww(__ldg(&be0[c])       + ssrc[c]);
        u64t init1 = pack_ww(__ldg(&be0[c + 128]) + ssrc[c + 128]);
        #pragma unroll
        for (int q = 0; q < 8; q++) { acc0[q] = init0; acc1[q] = init1; }
        #pragma unroll 4
        for (int k = 0; k < 128; k++) {
            u64t w0 = pack_ww(__ldg(&We0[k*DEHv + c]));
            u64t w1 = pack_ww(__ldg(&We0[k*DEHv + c + 128]));
            const float4* e4 = (const float4*)(secatT + k*36 + jg*16);
            #pragma unroll
            for (int q4 = 0; q4 < 4; q4++) {
                F4u ev; ev.v = e4[q4];
                ffma2(acc0[q4*2],   ev.p[0], w0);
                ffma2(acc0[q4*2+1], ev.p[1], w0);
                ffma2(acc1[q4*2],   ev.p[0], w1);
                ffma2(acc1[q4*2+1], ev.p[1], w1);
            }
        }
        #pragma unroll
        for (int q = 0; q < 8; q++) {
            int jj = jg*16 + 2*q;
            size_t tb0 = (size_t)(b*NNODE + j0 + jj)*DEHv;
            size_t tb1 = (size_t)(b*NNODE + j0 + jj + 1)*DEHv;
            U2u u0; u0.p = acc0[q];
            shT[c*36 + jj]     = gelu_f(u0.f[0] + __ldg(&g_tgt[tb0 + c]));
            shT[c*36 + jj + 1] = gelu_f(u0.f[1] + __ldg(&g_tgt[tb1 + c]));
            U2u u1; u1.p = acc1[q];
            shT[(c+128)*36 + jj]     = gelu_f(u1.f[0] + __ldg(&g_tgt[tb0 + c + 128]));
            shT[(c+128)*36 + jj + 1] = gelu_f(u1.f[1] + __ldg(&g_tgt[tb1 + c + 128]));
        }
    }
    __syncthreads();

    // e_pre = e + h @ We1 + be1  (32 x 64), K-split 2 x row-split 2 (R=16)
    {
        int c = t & 63, g = t >> 6;
        int rh = g & 1, kg = g >> 1;
        u64t acc[8];
        #pragma unroll
        for (int n = 0; n < 8; n++) acc[n] = 0ull;
        int kbeg = kg*128;
        #pragma unroll 8
        for (int kk = 0; kk < 128; kk++) {
            int k = kbeg + kk;
            u64t ww = pack_ww(__ldg(&We1[k*64 + c]));
            const float4* h4 = (const float4*)(shT + k*36 + rh*16);
            F4u a0, a1, a2, a3; a0.v = h4[0]; a1.v = h4[1]; a2.v = h4[2]; a3.v = h4[3];
            ffma2(acc[0], a0.p[0], ww); ffma2(acc[1], a0.p[1], ww);
            ffma2(acc[2], a1.p[0], ww); ffma2(acc[3], a1.p[1], ww);
            ffma2(acc[4], a2.p[0], ww); ffma2(acc[5], a2.p[1], ww);
            ffma2(acc[6], a3.p[0], ww); ffma2(acc[7], a3.p[1], ww);
        }
        u64t* scr = (u64t*)stT;  // stT not yet written; free as scratch
        if (kg == 1) {
            #pragma unroll
            for (int n = 0; n < 8; n++) scr[(n*2 + rh)*64 + c] = acc[n];
        }
        __syncthreads();
        if (kg == 0) {
            float bb1 = __ldg(&be1[c]);
            #pragma unroll
            for (int n = 0; n < 8; n++) {
                U2u u; u.p = acc[n];
                U2u v; v.p = scr[(n*2 + rh)*64 + c];
                int jj = rh*16 + 2*n;
                stRM[jj*64 + c]     = u.f[0] + v.f[0] + bb1 + eread[((size_t)bi*NNODE + j0 + jj)*DEv + c];
                stRM[(jj+1)*64 + c] = u.f[1] + v.f[1] + bb1 + eread[((size_t)bi*NNODE + j0 + jj + 1)*DEv + c];
            }
        }
    }
    __syncthreads();

    // LN0 per 64-wide row -> stRM (normalized) and stT (transposed)
    {
        int warp = t >> 5, lane = t & 31;
        for (int r = warp; r < 32; r += 8) {
            float a = stRM[r*64 + lane], q = stRM[r*64 + 32 + lane];
            float s = a + q, ss = a*a + q*q;
            #pragma unroll
            for (int off = 16; off; off >>= 1) {
                s  += __shfl_xor_sync(0xffffffffu, s, off);
                ss += __shfl_xor_sync(0xffffffffu, ss, off);
            }
            float mean = s * (1.f/64.f);
            float var = ss * (1.f/64.f) - mean*mean;
            float rstd = rsqrtf(var + 1e-5f);
            float y0 = (a - mean)*rstd*__ldg(&g0[lane])      + __ldg(&b0[lane]);
            float y1 = (q - mean)*rstd*__ldg(&g0[lane + 32]) + __ldg(&b0[lane + 32]);
            stRM[r*64 + lane] = y0; stRM[r*64 + 32 + lane] = y1;
            stT[lane*36 + r] = y0; stT[(lane + 32)*36 + r] = y1;
        }
    }
    __syncthreads();

    // hidden2 = gelu(e_new @ Wem1)   (32 x 256), reuse shT; C=2 cols x 16 rows
    {
        int c = t & 127;
        int jg = t >> 7;
        u64t acc0[8], acc1[8];
        #pragma unroll
        for (int q = 0; q < 8; q++) { acc0[q] = 0ull; acc1[q] = 0ull; }
        #pragma unroll 4
        for (int k = 0; k < 64; k++) {
            u64t w0 = pack_ww(__ldg(&Wem1[k*DEHv + c]));
            u64t w1 = pack_ww(__ldg(&Wem1[k*DEHv + c + 128]));
            const float4* e4 = (const float4*)(stT + k*36 + jg*16);
            #pragma unroll
            for (int q4 = 0; q4 < 4; q4++) {
                F4u ev; ev.v = e4[q4];
                ffma2(acc0[q4*2],   ev.p[0], w0);
                ffma2(acc0[q4*2+1], ev.p[1], w0);
                ffma2(acc1[q4*2],   ev.p[0], w1);
                ffma2(acc1[q4*2+1], ev.p[1], w1);
            }
        }
        #pragma unroll
        for (int q = 0; q < 8; q++) {
            int jj = jg*16 + 2*q;
            U2u u0; u0.p = acc0[q];
            shT[c*36 + jj]     = gelu_f(u0.f[0]);
            shT[c*36 + jj + 1] = gelu_f(u0.f[1]);
            U2u u1; u1.p = acc1[q];
            shT[(c+128)*36 + jj]     = gelu_f(u1.f[0]);
            shT[(c+128)*36 + jj + 1] = gelu_f(u1.f[1]);
        }
    }
    __syncthreads();

    // r2 = e_new + hidden2 @ Wem2 + bem2  (32 x 64), K-split 2 x row-split 2
    {
        int c = t & 63, g = t >> 6;
        int rh = g & 1, kg = g >> 1;
        u64t acc[8];
        #pragma unroll
        for (int n = 0; n < 8; n++) acc[n] = 0ull;
        int kbeg = kg*128;
        #pragma unroll 8
        for (int kk = 0; kk < 128; kk++) {
            int k = kbeg + kk;
            u64t ww = pack_ww(__ldg(&Wem2[k*64 + c]));
            const float4* h4 = (const float4*)(shT + k*36 + rh*16);
            F4u a0, a1, a2, a3; a0.v = h4[0]; a1.v = h4[1]; a2.v = h4[2]; a3.v = h4[3];
            ffma2(acc[0], a0.p[0], ww); ffma2(acc[1], a0.p[1], ww);
            ffma2(acc[2], a1.p[0], ww); ffma2(acc[3], a1.p[1], ww);
            ffma2(acc[4], a2.p[0], ww); ffma2(acc[5], a2.p[1], ww);
            ffma2(acc[6], a3.p[0], ww); ffma2(acc[7], a3.p[1], ww);
        }
        u64t* scr = (u64t*)secatT;  // secatT free at this stage
        if (kg == 1) {
            #pragma unroll
            for (int n = 0; n < 8; n++) scr[(n*2 + rh)*64 + c] = acc[n];
        }
        __syncthreads();
        if (kg == 0) {
            float bb2 = __ldg(&bem2[c]);
            #pragma unroll
            for (int n = 0; n < 8; n++) {
                U2u u; u.p = acc[n];
                U2u v; v.p = scr[(n*2 + rh)*64 + c];
                int jj = rh*16 + 2*n;
                r2[jj*64 + c]     = u.f[0] + v.f[0] + bb2 + stRM[jj*64 + c];
                r2[(jj+1)*64 + c] = u.f[1] + v.f[1] + bb2 + stRM[(jj+1)*64 + c];
            }
        }
    }
    __syncthreads();

    // LN1 per row -> write out
    {
        int warp = t >> 5, lane = t & 31;
        for (int r = warp; r < 32; r += 8) {
            float a = r2[r*64 + lane], q = r2[r*64 + 32 + lane];
            float s = a + q, ss = a*a + q*q;
            #pragma unroll
            for (int off = 16; off; off >>= 1) {
                s  += __shfl_xor_sync(0xffffffffu, s, off);
                ss += __shfl_xor_sync(0xffffffffu, ss, off);
            }
            float mean = s * (1.f/64.f);
            float var = ss * (1.f/64.f) - mean*mean;
            float rstd = rsqrtf(var + 1e-5f);
            float y0 = (a - mean)*rstd*__ldg(&g1[lane])      + __ldg(&b1[lane]);
            float y1 = (q - mean)*rstd*__ldg(&g1[lane + 32]) + __ldg(&b1[lane + 32]);
            size_t orow = ((size_t)bi*NNODE + j0 + r)*DEv;
            ewrite[orow + lane] = y0;
            ewrite[orow + 32 + lane] = y1;
        }
    }
}

// ---------------- host launcher ----------------------------------------------
extern "C" void kernel_launch(void* const* d_in, const int* in_sizes, int n_in,
                              void* d_out, int out_size) {
    const float* node   = (const float*)d_in[0];
    const float* edge   = (const float*)d_in[1];
    const float* Wqkv_n = (const float*)d_in[2];
    const float* Wqkv_e = (const float*)d_in[3];
    const float* Wo     = (const float*)d_in[4];
    const float* bo     = (const float*)d_in[5];
    const float* Wl0    = (const float*)d_in[6];
    const float* bl0    = (const float*)d_in[7];
    const float* ln0_g  = (const float*)d_in[8];
    const float* ln0_b  = (const float*)d_in[9];
    const float* Wm1    = (const float*)d_in[10];
    const float* Wm2    = (const float*)d_in[11];
    const float* bm2    = (const float*)d_in[12];
    const float* ln1_g  = (const float*)d_in[13];
    const float* ln1_b  = (const float*)d_in[14];
    const float* We0    = (const float*)d_in[15];
    const float* be0    = (const float*)d_in[16];
    const float* Ws     = (const float*)d_in[17];
    const float* bs     = (const float*)d_in[18];
    const float* Wt     = (const float*)d_in[19];
    const float* bt     = (const float*)d_in[20];
    const float* We1    = (const float*)d_in[21];
    const float* be1    = (const float*)d_in[22];
    const float* eln0_g = (const float*)d_in[23];
    const float* eln0_b = (const float*)d_in[24];
    const float* Wem1   = (const float*)d_in[25];
    const float* Wem2   = (const float*)d_in[26];
    const float* bem2   = (const float*)d_in[27];
    const float* eln1_g = (const float*)d_in[28];
    const float* eln1_b = (const float*)d_in[29];
    float* out = (float*)d_out;

    cudaFuncSetAttribute(k_attn, cudaFuncAttributeMaxDynamicSharedMemorySize, SMEM_ATTN);
    cudaFuncSetAttribute(k_edge, cudaFuncAttributeMaxDynamicSharedMemorySize, SMEM_EDGE);

    float* ebuf = nullptr;
    cudaGetSymbolAddress((void**)&ebuf, g_ebuf);
    float* out_e = out + BB*NNODE*DNv;   // e region of d_out

    k_copy_in<<<64, 256>>>((const float4*)node);
    k_qkvn<<<BB*NNODE, 128>>>(Wqkv_n);  // layer 0 qkv

    for (int l = 0; l < NLAYER; l++) {
        int has_next = (l + 1 < NLAYER);
        int ln = has_next ? l + 1 : l;
        // e buffer chain: input edge -> g_ebuf -> d_out e-region
        const float* eread = (l == 0) ? edge : ebuf;
        float* ewrite = has_next ? ebuf : out_e;
        k_attn<<<BB*NNODE, 256, SMEM_ATTN>>>(Wqkv_e + (size_t)l*DEv*4*DHv, eread);
        k_node1<<<BB*NNODE, 128>>>(Wo + (size_t)l*DHv*DNv, bo + l*DNv,
                                   Wl0 + (size_t)l*DNv*DNv, bl0 + l*DNv,
                                   ln0_g + l*DNv, ln0_b + l*DNv);
        k_node2<<<BB*NNODE, 128>>>(Wm1 + (size_t)l*DNv*DNHv, Wm2 + (size_t)l*DNHv*DNv,
                                   bm2 + l*DNv, ln1_g + l*DNv, ln1_b + l*DNv,
                                   out, has_next ? 0 : 1);
        k_aux<<<BB*NNODE*2, 256>>>(Ws + (size_t)l*DNv*DEHv, bs + l*DEHv,
                                   Wt + (size_t)l*DNv*DEHv, bt + l*DEHv,
                                   Wqkv_n + (size_t)ln*DNv*3*DHv, has_next);
        k_edge<<<BB*NNODE*8, 256, SMEM_EDGE>>>(
            We0 + (size_t)l*2*DEv*DEHv, be0 + l*DEHv,
            We1 + (size_t)l*DEHv*DEv,  be1 + l*DEv,
            eln0_g + l*DEv, eln0_b + l*DEv,
            Wem1 + (size_t)l*DEv*DEHv, Wem2 + (size_t)l*DEHv*DEv,
            bem2 + l*DEv, eln1_g + l*DEv, eln1_b + l*DEv,
            eread, ewrite);
    }
}

// round 13
// speedup vs baseline: 1.0342x; 1.0342x over previous
#include <cuda_runtime.h>
#include <math.h>

// dims
#define BB   2
#define NNODE 256
#define DNv  128
#define DEv  64
#define DHv  128
#define Hh   8
#define DHHv 16
#define DNHv 512
#define DEHv 256
#define NLAYER 2
#define ATT_SCALE 0.088388347648318447f  // 1/sqrt(128)

typedef unsigned long long u64t;

// packed fp32x2 FMA (Blackwell): one issue slot, two fp32 FMAs, exact .rn numerics
__device__ __forceinline__ void ffma2(u64t& acc, u64t a, u64t b) {
    asm("fma.rn.f32x2 %0, %1, %2, %0;" : "+l"(acc) : "l"(a), "l"(b));
}
__device__ __forceinline__ u64t pack_ww(float w) {
    u64t r; asm("mov.b64 %0, {%1, %1};" : "=l"(r) : "f"(w)); return r;
}
union F4u { float4 v; u64t p[2]; };
union U2u { u64t p; float f[2]; };

// ---------------- scratch (device globals; no allocations allowed) ----------
__device__ float g_x[BB*NNODE*DNv];
__device__ float g_ebuf[BB*NNODE*NNODE*DEv];   // intermediate e (after layer 0)
__device__ float g_qkvn[BB*NNODE*3*DHv];
__device__ float g_attnout[BB*NNODE*DHv];
__device__ float g_src[BB*NNODE*DEHv];
__device__ float g_tgt[BB*NNODE*DEHv];

__device__ __forceinline__ float gelu_f(float x) {
    return 0.5f * x * (1.0f + erff(x * 0.70710678118654752440f));
}

// ---------------- copy in: node features only --------------------------------
__global__ void k_copy_in(const float4* __restrict__ node) {
    int tid = blockIdx.x * blockDim.x + threadIdx.x;
    float4* x4 = (float4*)g_x;
    if (tid < BB*NNODE*DNv/4) x4[tid] = node[tid];
}

// ---------------- qkv_n for layer 0 only -------------------------------------
__global__ void k_qkvn(const float* __restrict__ W) {  // W: [128][384]
    __shared__ float sx[DNv];
    int row = blockIdx.x;
    int t = threadIdx.x;   // 128 threads
    sx[t] = g_x[row*DNv + t];
    __syncthreads();
    for (int c = t; c < 3*DHv; c += 128) {
        float acc = 0.f;
        #pragma unroll 16
        for (int k = 0; k < DNv; k++) acc += sx[k] * __ldg(&W[k*384 + c]);
        g_qkvn[row*384 + c] = acc;
    }
}

// ---------------- fused attention: per (b,i), flash-style over j -------------
// R10 structure (occ 2) + double-buffered seT with register prefetch of the
// next e-tile issued before the GEMM (hides the global-load latency).
#define SE_STR 385
#define KV_STR 132
#define SET_HALF (64*36)
#define SMEM_ATTN ((32*SE_STR + 2*SET_HALF + 32*KV_STR + 32*KV_STR + 128 + 8*65 + 8*36) * 4)
__global__ void __launch_bounds__(256, 2) k_attn(const float* __restrict__ We,
                                                 const float* __restrict__ eread) {
    extern __shared__ float sm[];
    float* sE  = sm;                   // logical-col E tile, stride 385
    float* seT = sE  + 32*SE_STR;      // e tile transposed, DOUBLE buffer [2][64][36]
    float* skn = seT + 2*SET_HALF;     // kn tile [jj][128], stride 132
    float* svn = skn + 32*KV_STR;      // vn tile
    float* sq  = svn + 32*KV_STR;      // q row (128)
    float* sf  = sq + 128;             // f per head [8][65]
    float* sp  = sf + 8*65;            // p per head [8][36]

    int b = blockIdx.x / NNODE, i = blockIdx.x % NNODE;
    int t = threadIdx.x, warp = t >> 5, lane = t & 31;
    int h = warp;  // 8 warps = 8 heads
    int dd = lane & 15, hi = lane >> 4;  // AV split: lane half 'hi' owns j-rows hi*16..

    // E-GEMM worker mapping: rows rh*16..+15, logical cols cb, cb+128, cb+256
    int rh = t >> 7, cb = t & 127;
    int ac0, ac1, ac2;
    {
        int L0 = cb, L1 = cb + 128, L2 = cb + 256;
        int w0 = L0 % 48, w1 = L1 % 48, w2 = L2 % 48;
        ac0 = (L0/48)*64 + (w0 < 32 ? w0 : w0 + 16);
        ac1 = (L1/48)*64 + (w1 < 32 ? w1 : w1 + 16);
        ac2 = (L2/48)*64 + (w2 < 32 ? w2 : w2 + 16);
    }
    // prefetch/store indexing (8 elements per thread per tile)
    int pjj = t >> 6, pc = t & 63;     // element u: row pjj + (u&3)*8? keep simple: idx = t + u*256

    if (t < DHv) { int hh = t >> 4, d = t & 15; sq[t] = g_qkvn[(b*NNODE + i)*384 + hh*48 + d]; }

    float m = -3.4e38f, lsum = 0.f, o = 0.f;
    float f0 = 0.f, f1 = 0.f;           // f cols: lane, lane+32
    const float* erow = eread + (size_t)(b*NNODE + i) * NNODE * DEv;

    // preload tile 0 into seT buffer 0
    for (int idx = t; idx < 32*64; idx += 256) {
        int jj = idx >> 6, c = idx & 63;
        seT[c*36 + jj] = erow[jj*DEv + c];
    }
    int cur = 0;

    for (int j0 = 0; j0 < NNODE; j0 += 32) {
        float* seTc = seT + cur*SET_HALF;
        float* seTn = seT + (cur^1)*SET_HALF;
        __syncthreads();  // prev tile readers done; seTc (stored last iter) visible
        // load kn, vn tiles (float4: 32 rows x 8 heads x 4 f4-units)
        #pragma unroll
        for (int u = 0; u < 4; u++) {
            int idx = t + u*256;
            int jj = idx >> 5, uu = idx & 31;
            int hh = uu >> 2, q4u = uu & 3;
            const float4* src = (const float4*)(g_qkvn + (size_t)(b*NNODE + j0 + jj)*384 + hh*48 + 16);
            ((float4*)(skn + jj*KV_STR + hh*16))[q4u] = __ldg(&src[q4u]);
            ((float4*)(svn + jj*KV_STR + hh*16))[q4u] = __ldg(&src[4 + q4u]);
        }
        // issue prefetch LDGs for next e tile (consumed after the GEMM)
        float pf[8];
        int jn = j0 + 32;
        if (jn < NNODE) {
            #pragma unroll
            for (int u = 0; u < 8; u++) {
                int idx = t + u*256;
                int jj = idx >> 6, c = idx & 63;
                pf[u] = __ldg(&erow[(jn + jj)*DEv + c]);
            }
        }
        __syncthreads();  // skn/svn ready
        // E = e_tile @ Wqkv_e[eq,ek,em]  (32 x 384): all 256 threads,
        // 3 cols x 16 rows each
        {
            u64t a0[8], a1[8], a2[8];
            #pragma unroll
            for (int q = 0; q < 8; q++) { a0[q] = 0ull; a1[q] = 0ull; a2[q] = 0ull; }
            #pragma unroll 4
            for (int k = 0; k < 64; k++) {
                u64t w0 = pack_ww(__ldg(&We[k*512 + ac0]));
                u64t w1 = pack_ww(__ldg(&We[k*512 + ac1]));
                u64t w2 = pack_ww(__ldg(&We[k*512 + ac2]));
                const float4* e4 = (const float4*)(seTc + k*36 + rh*16);
                #pragma unroll
                for (int q4 = 0; q4 < 4; q4++) {
                    F4u ev; ev.v = e4[q4];
                    ffma2(a0[q4*2],   ev.p[0], w0);
                    ffma2(a0[q4*2+1], ev.p[1], w0);
                    ffma2(a1[q4*2],   ev.p[0], w1);
                    ffma2(a1[q4*2+1], ev.p[1], w1);
                    ffma2(a2[q4*2],   ev.p[0], w2);
                    ffma2(a2[q4*2+1], ev.p[1], w2);
                }
            }
            #pragma unroll
            for (int q = 0; q < 8; q++) {
                int row = rh*16 + 2*q;
                U2u u0; u0.p = a0[q];
                sE[row*SE_STR + cb]       = u0.f[0];
                sE[(row+1)*SE_STR + cb]   = u0.f[1];
                U2u u1; u1.p = a1[q];
                sE[row*SE_STR + cb+128]     = u1.f[0];
                sE[(row+1)*SE_STR + cb+128] = u1.f[1];
                U2u u2; u2.p = a2[q];
                sE[row*SE_STR + cb+256]     = u2.f[0];
                sE[(row+1)*SE_STR + cb+256] = u2.f[1];
            }
        }
        // store prefetched next e tile into the other buffer (LDG latency now hidden)
        if (jn < NNODE) {
            #pragma unroll
            for (int u = 0; u < 8; u++) {
                int idx = t + u*256;
                int jj = idx >> 6, c = idx & 63;
                seTn[c*36 + jj] = pf[u];
            }
        }
        __syncthreads();  // sE ready
        // dots (lane = j within tile), online softmax per warp/head
        const float* Er = sE + lane*SE_STR + h*48;
        const float* kr = skn + lane*KV_STR + h*16;
        float dot = 0.f;
        #pragma unroll
        for (int d = 0; d < 16; d++)
            dot += (sq[h*16 + d] + Er[d]) * (kr[d] + Er[16 + d]);
        dot *= ATT_SCALE;
        float mt = dot;
        #pragma unroll
        for (int off = 16; off; off >>= 1) mt = fmaxf(mt, __shfl_xor_sync(0xffffffffu, mt, off));
        float mnew = fmaxf(m, mt);
        float p = expf(dot - mnew);
        float corr = expf(m - mnew);   // first tile: exp(-huge) = 0
        float ps = p;
        #pragma unroll
        for (int off = 16; off; off >>= 1) ps += __shfl_xor_sync(0xffffffffu, ps, off);
        lsum = lsum * corr + ps;
        o *= corr; f0 *= corr; f1 *= corr;
        // stage p for this warp's tile (own row; syncwarp is enough)
        sp[h*36 + lane] = p;
        __syncwarp();
        // f accumulation, float4 over j (seTc rows are j-contiguous)
        {
            const float4* pv4 = (const float4*)(sp + h*36);
            const float4* e0v = (const float4*)(seTc + lane*36);
            const float4* e1v = (const float4*)(seTc + (lane + 32)*36);
            #pragma unroll
            for (int jq = 0; jq < 8; jq++) {
                float4 pv = pv4[jq];
                float4 a = e0v[jq], bq = e1v[jq];
                f0 += pv.x*a.x + pv.y*a.y + pv.z*a.z + pv.w*a.w;
                f1 += pv.x*bq.x + pv.y*bq.y + pv.z*bq.z + pv.w*bq.w;
            }
        }
        // o[d] += sum_j p_j * vn[j,d]*em[j,d] — j split by lane-half
        #pragma unroll
        for (int jj = 0; jj < 16; jj++) {
            int jjj = hi*16 + jj;
            float pj = __shfl_sync(0xffffffffu, p, jjj);
            const float* Ej = sE + jjj*SE_STR + h*48;
            o += pj * (svn[jjj*KV_STR + h*16 + dd] * Ej[32 + dd]);
        }
        m = mnew;
        cur ^= 1;
    }
    // combine the two j-halves of o
    float of = o + __shfl_xor_sync(0xffffffffu, o, 16);
    // stash f for this head, then apply Wev projection (exact linear reorder)
    sf[h*65 + lane] = f0;
    sf[h*65 + 32 + lane] = f1;
    __syncwarp();
    if (lane < 16) {
        float fv = 0.f;
        #pragma unroll 8
        for (int c = 0; c < 64; c++)
            fv += sf[h*65 + c] * __ldg(&We[c*512 + h*64 + 32 + lane]);
        g_attnout[(b*NNODE + i)*DHv + h*16 + lane] = (of + fv) / lsum;
    }
}

// ---------------- LayerNorm helper for 128-wide rows (128 threads) -----------
__device__ __forceinline__ float ln128(float r, const float* __restrict__ g,
                                       const float* __restrict__ bta, float* sred, int t) {
    __syncthreads();  // protect sred reuse
    int warp = t >> 5, lane = t & 31;
    float s = r, ss = r*r;
    #pragma unroll
    for (int off = 16; off; off >>= 1) {
        s  += __shfl_xor_sync(0xffffffffu, s, off);
        ss += __shfl_xor_sync(0xffffffffu, ss, off);
    }
    if (lane == 0) { sred[warp] = s; sred[4 + warp] = ss; }
    __syncthreads();
    if (t == 0) {
        float S = sred[0]+sred[1]+sred[2]+sred[3];
        float SS = sred[4]+sred[5]+sred[6]+sred[7];
        float mean = S * (1.f/128.f);
        float var = SS * (1.f/128.f) - mean*mean;
        sred[8] = mean;
        sred[9] = rsqrtf(var + 1e-5f);
    }
    __syncthreads();
    return (r - sred[8]) * sred[9] * g[t] + bta[t];
}

// ---------------- node update 1: x = ln(x + (attn@Wo+bo)@Wl0 + bl0) ----------
__global__ void k_node1(const float* __restrict__ Wo, const float* __restrict__ bo,
                        const float* __restrict__ Wl0, const float* __restrict__ bl0,
                        const float* __restrict__ gam, const float* __restrict__ bet) {
    __shared__ float sa[DHv];
    __shared__ float st[DNv];
    __shared__ float sred[10];
    int row = blockIdx.x; int t = threadIdx.x;
    sa[t] = g_attnout[row*DHv + t];
    __syncthreads();
    float acc = bo[t];
    #pragma unroll 16
    for (int k = 0; k < DHv; k++) acc += sa[k] * __ldg(&Wo[k*DNv + t]);
    st[t] = acc;
    __syncthreads();
    float u = bl0[t];
    #pragma unroll 16
    for (int k = 0; k < DNv; k++) u += st[k] * __ldg(&Wl0[k*DNv + t]);
    float r = g_x[row*DNv + t] + u;
    g_x[row*DNv + t] = ln128(r, gam, bet, sred, t);
}

// ---------------- node MLP: x = ln(x + gelu(x@Wm1)@Wm2 + bm2) ----------------
// wout: also write final x into xout (d_out) on the last layer
__global__ void k_node2(const float* __restrict__ Wm1, const float* __restrict__ Wm2,
                        const float* __restrict__ bm2,
                        const float* __restrict__ gam, const float* __restrict__ bet,
                        float* __restrict__ xout, int wout) {
    __shared__ float sx[DNv];
    __shared__ float sh[DNHv];
    __shared__ float sred[10];
    int row = blockIdx.x; int t = threadIdx.x;
    float xv = g_x[row*DNv + t];
    sx[t] = xv;
    __syncthreads();
    for (int c = t; c < DNHv; c += 128) {
        float acc = 0.f;
        #pragma unroll 16
        for (int k = 0; k < DNv; k++) acc += sx[k] * __ldg(&Wm1[k*DNHv + c]);
        sh[c] = gelu_f(acc);
    }
    __syncthreads();
    float u = bm2[t];
    #pragma unroll 16
    for (int k = 0; k < DNHv; k++) u += sh[k] * __ldg(&Wm2[k*DNv + t]);
    float r = xv + u;
    float y = ln128(r, gam, bet, sred, t);
    g_x[row*DNv + t] = y;
    if (wout) xout[row*DNv + t] = y;
}

// ---------------- aux: srctgt (blocks 0..511) + next-layer qkvn (512..1023) --
__global__ void k_aux(const float* __restrict__ Ws, const float* __restrict__ bs,
                      const float* __restrict__ Wt, const float* __restrict__ bt,
                      const float* __restrict__ Wqn, int do_qkv) {
    __shared__ float sx[DNv];
    int t = threadIdx.x;  // 256 threads
    if (blockIdx.x < BB*NNODE) {
        int row = blockIdx.x;
        if (t < DNv) sx[t] = g_x[row*DNv + t];
        __syncthreads();
        float a = bs[t], c2 = bt[t];
        #pragma unroll 16
        for (int k = 0; k < DNv; k++) {
            float xv = sx[k];
            a  += xv * __ldg(&Ws[k*DEHv + t]);
            c2 += xv * __ldg(&Wt[k*DEHv + t]);
        }
        g_src[row*DEHv + t] = a;
        g_tgt[row*DEHv + t] = c2;
    } else {
        if (!do_qkv) return;
        int row = blockIdx.x - BB*NNODE;
        if (t < DNv) sx[t] = g_x[row*DNv + t];
        __syncthreads();
        for (int c = t; c < 3*DHv; c += 256) {
            float acc = 0.f;
            #pragma unroll 16
            for (int k = 0; k < DNv; k++) acc += sx[k] * __ldg(&Wqn[k*384 + c]);
            g_qkvn[row*384 + c] = acc;
        }
    }
}

// ---------------- fused edge update kernel -----------------------------------
// block = (b, i, j-tile of 32), 256 threads.  r2 aliases stT (disjoint lifetimes)
#define SMEM_EDGE ((128*36 + 256*36 + 2048 + 64*36 + 256) * 4)
__global__ void __launch_bounds__(256, 3) k_edge(
                       const float* __restrict__ We0, const float* __restrict__ be0,
                       const float* __restrict__ We1, const float* __restrict__ be1,
                       const float* __restrict__ g0, const float* __restrict__ b0,
                       const float* __restrict__ Wem1, const float* __restrict__ Wem2,
                       const float* __restrict__ bem2,
                       const float* __restrict__ g1, const float* __restrict__ b1,
                       const float* __restrict__ eread, float* __restrict__ ewrite) {
    extern __shared__ float sm[];
    float* secatT = sm;                 // [k=128][jj=32] stride 36
    float* shT    = secatT + 128*36;    // [k=256][jj=32] stride 36
    float* stRM   = shT + 256*36;       // [jj=32][c=64] row-major
    float* stT    = stRM + 2048;        // [k=64][jj=32] stride 36
    float* r2     = stT;                // ALIAS: r2 live only after stT is dead
    float* ssrc   = stT + 64*36;        // 256

    int jt = blockIdx.x & 7;
    int bi = blockIdx.x >> 3;           // b*N+i
    int b = bi >> 8, i = bi & 255;
    int j0 = jt * 32;
    int t = threadIdx.x;

    // load ecat = [e_ij, e_ji] transposed
    for (int idx = t; idx < 32*64; idx += 256) {
        int jj = idx >> 6, c = idx & 63;
        secatT[c*36 + jj]        = eread[((size_t)bi*NNODE + j0 + jj)*DEv + c];
        secatT[(64 + c)*36 + jj] = eread[((size_t)(b*NNODE + j0 + jj)*NNODE + i)*DEv + c];
    }
    ssrc[t] = g_src[(size_t)bi*DEHv + t];
    __syncthreads();

    // h = gelu(ecat @ We0 + be0 + src_i + tgt_j)   (32 x 256), C=2 cols x 16 rows
    {
        int c = t & 127;     // cols c and c+128
        int jg = t >> 7;     // row-half: rows jg*16 .. jg*16+15
        u64t acc0[8], acc1[8];
        u64t init0 = pack_ww(__ldg(&be0[c])       + ssrc[c]);
        u64t init1 = pack_ww(__ldg(&be0[c + 128]) + ssrc[c + 128]);
        #pragma unroll
        for (int q = 0; q < 8; q++) { acc0[q] = init0; acc1[q] = init1; }
        #pragma unroll 4
        for (int k = 0; k < 128; k++) {
            u64t w0 = pack_ww(__ldg(&We0[k*DEHv + c]));
            u64t w1 = pack_ww(__ldg(&We0[k*DEHv + c + 128]));
            const float4* e4 = (const float4*)(secatT + k*36 + jg*16);
            #pragma unroll
            for (int q4 = 0; q4 < 4; q4++) {
                F4u ev; ev.v = e4[q4];
                ffma2(acc0[q4*2],   ev.p[0], w0);
                ffma2(acc0[q4*2+1], ev.p[1], w0);
                ffma2(acc1[q4*2],   ev.p[0], w1);
                ffma2(acc1[q4*2+1], ev.p[1], w1);
            }
        }
        #pragma unroll
        for (int q = 0; q < 8; q++) {
            int jj = jg*16 + 2*q;
            size_t tb0 = (size_t)(b*NNODE + j0 + jj)*DEHv;
            size_t tb1 = (size_t)(b*NNODE + j0 + jj + 1)*DEHv;
            U2u u0; u0.p = acc0[q];
            shT[c*36 + jj]     = gelu_f(u0.f[0] + __ldg(&g_tgt[tb0 + c]));
            shT[c*36 + jj + 1] = gelu_f(u0.f[1] + __ldg(&g_tgt[tb1 + c]));
            U2u u1; u1.p = acc1[q];
            shT[(c+128)*36 + jj]     = gelu_f(u1.f[0] + __ldg(&g_tgt[tb0 + c + 128]));
            shT[(c+128)*36 + jj + 1] = gelu_f(u1.f[1] + __ldg(&g_tgt[tb1 + c + 128]));
        }
    }
    __syncthreads();

    // e_pre = e + h @ We1 + be1  (32 x 64), K-split 2 x row-split 2 (R=16)
    {
        int c = t & 63, g = t >> 6;
        int rh = g & 1, kg = g >> 1;
        u64t acc[8];
        #pragma unroll
        for (int n = 0; n < 8; n++) acc[n] = 0ull;
        int kbeg = kg*128;
        #pragma unroll 8
        for (int kk = 0; kk < 128; kk++) {
            int k = kbeg + kk;
            u64t ww = pack_ww(__ldg(&We1[k*64 + c]));
            const float4* h4 = (const float4*)(shT + k*36 + rh*16);
            F4u a0, a1, a2, a3; a0.v = h4[0]; a1.v = h4[1]; a2.v = h4[2]; a3.v = h4[3];
            ffma2(acc[0], a0.p[0], ww); ffma2(acc[1], a0.p[1], ww);
            ffma2(acc[2], a1.p[0], ww); ffma2(acc[3], a1.p[1], ww);
            ffma2(acc[4], a2.p[0], ww); ffma2(acc[5], a2.p[1], ww);
            ffma2(acc[6], a3.p[0], ww); ffma2(acc[7], a3.p[1], ww);
        }
        u64t* scr = (u64t*)stT;  // stT not yet written; free as scratch
        if (kg == 1) {
            #pragma unroll
            for (int n = 0; n < 8; n++) scr[(n*2 + rh)*64 + c] = acc[n];
        }
        __syncthreads();
        if (kg == 0) {
            float bb1 = __ldg(&be1[c]);
            #pragma unroll
            for (int n = 0; n < 8; n++) {
                U2u u; u.p = acc[n];
                U2u v; v.p = scr[(n*2 + rh)*64 + c];
                int jj = rh*16 + 2*n;
                stRM[jj*64 + c]     = u.f[0] + v.f[0] + bb1 + eread[((size_t)bi*NNODE + j0 + jj)*DEv + c];
                stRM[(jj+1)*64 + c] = u.f[1] + v.f[1] + bb1 + eread[((size_t)bi*NNODE + j0 + jj + 1)*DEv + c];
            }
        }
    }
    __syncthreads();

    // LN0 per 64-wide row -> stRM (normalized) and stT (transposed)
    {
        int warp = t >> 5, lane = t & 31;
        for (int r = warp; r < 32; r += 8) {
            float a = stRM[r*64 + lane], q = stRM[r*64 + 32 + lane];
            float s = a + q, ss = a*a + q*q;
            #pragma unroll
            for (int off = 16; off; off >>= 1) {
                s  += __shfl_xor_sync(0xffffffffu, s, off);
                ss += __shfl_xor_sync(0xffffffffu, ss, off);
            }
            float mean = s * (1.f/64.f);
            float var = ss * (1.f/64.f) - mean*mean;
            float rstd = rsqrtf(var + 1e-5f);
            float y0 = (a - mean)*rstd*__ldg(&g0[lane])      + __ldg(&b0[lane]);
            float y1 = (q - mean)*rstd*__ldg(&g0[lane + 32]) + __ldg(&b0[lane + 32]);
            stRM[r*64 + lane] = y0; stRM[r*64 + 32 + lane] = y1;
            stT[lane*36 + r] = y0; stT[(lane + 32)*36 + r] = y1;
        }
    }
    __syncthreads();

    // hidden2 = gelu(e_new @ Wem1)   (32 x 256), reuse shT; C=2 cols x 16 rows
    {
        int c = t & 127;
        int jg = t >> 7;
        u64t acc0[8], acc1[8];
        #pragma unroll
        for (int q = 0; q < 8; q++) { acc0[q] = 0ull; acc1[q] = 0ull; }
        #pragma unroll 4
        for (int k = 0; k < 64; k++) {
            u64t w0 = pack_ww(__ldg(&Wem1[k*DEHv + c]));
            u64t w1 = pack_ww(__ldg(&Wem1[k*DEHv + c + 128]));
            const float4* e4 = (const float4*)(stT + k*36 + jg*16);
            #pragma unroll
            for (int q4 = 0; q4 < 4; q4++) {
                F4u ev; ev.v = e4[q4];
                ffma2(acc0[q4*2],   ev.p[0], w0);
                ffma2(acc0[q4*2+1], ev.p[1], w0);
                ffma2(acc1[q4*2],   ev.p[0], w1);
                ffma2(acc1[q4*2+1], ev.p[1], w1);
            }
        }
        #pragma unroll
        for (int q = 0; q < 8; q++) {
            int jj = jg*16 + 2*q;
            U2u u0; u0.p = acc0[q];
            shT[c*36 + jj]     = gelu_f(u0.f[0]);
            shT[c*36 + jj + 1] = gelu_f(u0.f[1]);
            U2u u1; u1.p = acc1[q];
            shT[(c+128)*36 + jj]     = gelu_f(u1.f[0]);
            shT[(c+128)*36 + jj + 1] = gelu_f(u1.f[1]);
        }
    }
    __syncthreads();

    // r2 = e_new + hidden2 @ Wem2 + bem2  (32 x 64), K-split 2 x row-split 2
    {
        int c = t & 63, g = t >> 6;
        int rh = g & 1, kg = g >> 1;
        u64t acc[8];
        #pragma unroll
        for (int n = 0; n < 8; n++) acc[n] = 0ull;
        int kbeg = kg*128;
        #pragma unroll 8
        for (int kk = 0; kk < 128; kk++) {
            int k = kbeg + kk;
            u64t ww = pack_ww(__ldg(&Wem2[k*64 + c]));
            const float4* h4 = (const float4*)(shT + k*36 + rh*16);
            F4u a0, a1, a2, a3; a0.v = h4[0]; a1.v = h4[1]; a2.v = h4[2]; a3.v = h4[3];
            ffma2(acc[0], a0.p[0], ww); ffma2(acc[1], a0.p[1], ww);
            ffma2(acc[2], a1.p[0], ww); ffma2(acc[3], a1.p[1], ww);
            ffma2(acc[4], a2.p[0], ww); ffma2(acc[5], a2.p[1], ww);
            ffma2(acc[6], a3.p[0], ww); ffma2(acc[7], a3.p[1], ww);
        }
        u64t* scr = (u64t*)secatT;  // secatT free at this stage
        if (kg == 1) {
            #pragma unroll
            for (int n = 0; n < 8; n++) scr[(n*2 + rh)*64 + c] = acc[n];
        }
        __syncthreads();
        if (kg == 0) {
            float bb2 = __ldg(&bem2[c]);
            #pragma unroll
            for (int n = 0; n < 8; n++) {
                U2u u; u.p = acc[n];
                U2u v; v.p = scr[(n*2 + rh)*64 + c];
                int jj = rh*16 + 2*n;
                r2[jj*64 + c]     = u.f[0] + v.f[0] + bb2 + stRM[jj*64 + c];
                r2[(jj+1)*64 + c] = u.f[1] + v.f[1] + bb2 + stRM[(jj+1)*64 + c];
            }
        }
    }
    __syncthreads();

    // LN1 per row -> write out
    {
        int warp = t >> 5, lane = t & 31;
        for (int r = warp; r < 32; r += 8) {
            float a = r2[r*64 + lane], q = r2[r*64 + 32 + lane];
            float s = a + q, ss = a*a + q*q;
            #pragma unroll
            for (int off = 16; off; off >>= 1) {
                s  += __shfl_xor_sync(0xffffffffu, s, off);
                ss += __shfl_xor_sync(0xffffffffu, ss, off);
            }
            float mean = s * (1.f/64.f);
            float var = ss * (1.f/64.f) - mean*mean;
            float rstd = rsqrtf(var + 1e-5f);
            float y0 = (a - mean)*rstd*__ldg(&g1[lane])      + __ldg(&b1[lane]);
            float y1 = (q - mean)*rstd*__ldg(&g1[lane + 32]) + __ldg(&b1[lane + 32]);
            size_t orow = ((size_t)bi*NNODE + j0 + r)*DEv;
            ewrite[orow + lane] = y0;
            ewrite[orow + 32 + lane] = y1;
        }
    }
}

// ---------------- host launcher ----------------------------------------------
extern "C" void kernel_launch(void* const* d_in, const int* in_sizes, int n_in,
                              void* d_out, int out_size) {
    const float* node   = (const float*)d_in[0];
    const float* edge   = (const float*)d_in[1];
    const float* Wqkv_n = (const float*)d_in[2];
    const float* Wqkv_e = (const float*)d_in[3];
    const float* Wo     = (const float*)d_in[4];
    const float* bo     = (const float*)d_in[5];
    const float* Wl0    = (const float*)d_in[6];
    const float* bl0    = (const float*)d_in[7];
    const float* ln0_g  = (const float*)d_in[8];
    const float* ln0_b  = (const float*)d_in[9];
    const float* Wm1    = (const float*)d_in[10];
    const float* Wm2    = (const float*)d_in[11];
    const float* bm2    = (const float*)d_in[12];
    const float* ln1_g  = (const float*)d_in[13];
    const float* ln1_b  = (const float*)d_in[14];
    const float* We0    = (const float*)d_in[15];
    const float* be0    = (const float*)d_in[16];
    const float* Ws     = (const float*)d_in[17];
    const float* bs     = (const float*)d_in[18];
    const float* Wt     = (const float*)d_in[19];
    const float* bt     = (const float*)d_in[20];
    const float* We1    = (const float*)d_in[21];
    const float* be1    = (const float*)d_in[22];
    const float* eln0_g = (const float*)d_in[23];
    const float* eln0_b = (const float*)d_in[24];
    const float* Wem1   = (const float*)d_in[25];
    const float* Wem2   = (const float*)d_in[26];
    const float* bem2   = (const float*)d_in[27];
    const float* eln1_g = (const float*)d_in[28];
    const float* eln1_b = (const float*)d_in[29];
    float* out = (float*)d_out;

    cudaFuncSetAttribute(k_attn, cudaFuncAttributeMaxDynamicSharedMemorySize, SMEM_ATTN);
    cudaFuncSetAttribute(k_edge, cudaFuncAttributeMaxDynamicSharedMemorySize, SMEM_EDGE);

    float* ebuf = nullptr;
    cudaGetSymbolAddress((void**)&ebuf, g_ebuf);
    float* out_e = out + BB*NNODE*DNv;   // e region of d_out

    k_copy_in<<<64, 256>>>((const float4*)node);
    k_qkvn<<<BB*NNODE, 128>>>(Wqkv_n);  // layer 0 qkv

    for (int l = 0; l < NLAYER; l++) {
        int has_next = (l + 1 < NLAYER);
        int ln = has_next ? l + 1 : l;
        // e buffer chain: input edge -> g_ebuf -> d_out e-region
        const float* eread = (l == 0) ? edge : ebuf;
        float* ewrite = has_next ? ebuf : out_e;
        k_attn<<<BB*NNODE, 256, SMEM_ATTN>>>(Wqkv_e + (size_t)l*DEv*4*DHv, eread);
        k_node1<<<BB*NNODE, 128>>>(Wo + (size_t)l*DHv*DNv, bo + l*DNv,
                                   Wl0 + (size_t)l*DNv*DNv, bl0 + l*DNv,
                                   ln0_g + l*DNv, ln0_b + l*DNv);
        k_node2<<<BB*NNODE, 128>>>(Wm1 + (size_t)l*DNv*DNHv, Wm2 + (size_t)l*DNHv*DNv,
                                   bm2 + l*DNv, ln1_g + l*DNv, ln1_b + l*DNv,
                                   out, has_next ? 0 : 1);
        k_aux<<<BB*NNODE*2, 256>>>(Ws + (size_t)l*DNv*DEHv, bs + l*DEHv,
                                   Wt + (size_t)l*DNv*DEHv, bt + l*DEHv,
                                   Wqkv_n + (size_t)ln*DNv*3*DHv, has_next);
        k_edge<<<BB*NNODE*8, 256, SMEM_EDGE>>>(
            We0 + (size_t)l*2*DEv*DEHv, be0 + l*DEHv,
            We1 + (size_t)l*DEHv*DEv,  be1 + l*DEv,
            eln0_g + l*DEv, eln0_b + l*DEv,
            Wem1 + (size_t)l*DEv*DEHv, Wem2 + (size_t)l*DEHv*DEv,
            bem2 + l*DEv, eln1_g + l*DEv, eln1_b + l*DEv,
            eread, ewrite);
    }
}

// round 14
// speedup vs baseline: 1.0360x; 1.0018x over previous
#include <cuda_runtime.h>
#include <math.h>

// dims
#define BB   2
#define NNODE 256
#define DNv  128
#define DEv  64
#define DHv  128
#define Hh   8
#define DHHv 16
#define DNHv 512
#define DEHv 256
#define NLAYER 2
#define ATT_SCALE 0.088388347648318447f  // 1/sqrt(128)

typedef unsigned long long u64t;

// packed fp32x2 FMA (Blackwell): one issue slot, two fp32 FMAs, exact .rn numerics
__device__ __forceinline__ void ffma2(u64t& acc, u64t a, u64t b) {
    asm("fma.rn.f32x2 %0, %1, %2, %0;" : "+l"(acc) : "l"(a), "l"(b));
}
__device__ __forceinline__ u64t pack_ww(float w) {
    u64t r; asm("mov.b64 %0, {%1, %1};" : "=l"(r) : "f"(w)); return r;
}
union F4u { float4 v; u64t p[2]; };
union U2u { u64t p; float f[2]; };

// ---------------- scratch (device globals; no allocations allowed) ----------
__device__ float g_x[BB*NNODE*DNv];
__device__ float g_ebuf[BB*NNODE*NNODE*DEv];   // intermediate e (after layer 0)
__device__ float g_qkvn[BB*NNODE*3*DHv];
__device__ float g_src[BB*NNODE*DEHv];
__device__ float g_tgt[BB*NNODE*DEHv];

__device__ __forceinline__ float gelu_f(float x) {
    return 0.5f * x * (1.0f + erff(x * 0.70710678118654752440f));
}

// ---------------- copy in: node features only --------------------------------
__global__ void k_copy_in(const float4* __restrict__ node) {
    int tid = blockIdx.x * blockDim.x + threadIdx.x;
    float4* x4 = (float4*)g_x;
    if (tid < BB*NNODE*DNv/4) x4[tid] = node[tid];
}

// ---------------- qkv_n for layer 0 only -------------------------------------
__global__ void k_qkvn(const float* __restrict__ W) {  // W: [128][384]
    __shared__ float sx[DNv];
    int row = blockIdx.x;
    int t = threadIdx.x;   // 128 threads
    sx[t] = g_x[row*DNv + t];
    __syncthreads();
    for (int c = t; c < 3*DHv; c += 128) {
        float acc = 0.f;
        #pragma unroll 16
        for (int k = 0; k < DNv; k++) acc += sx[k] * __ldg(&W[k*384 + c]);
        g_qkvn[row*384 + c] = acc;
    }
}

// ---------------- fused attention + node1: per (b,i) -------------------------
// R12 structure (occ 2, double-buffered seT prefetch) + fused node1 epilogue:
// x = ln(x + (attnout@Wo+bo)@Wl0 + bl0) computed in-block (row fully owned).
#define SE_STR 385
#define KV_STR 132
#define SET_HALF (64*36)
#define SMEM_ATTN ((32*SE_STR + 2*SET_HALF + 32*KV_STR + 32*KV_STR + 128 + 8*65 + 8*36) * 4)
__global__ void __launch_bounds__(256, 2) k_attn(const float* __restrict__ We,
                                                 const float* __restrict__ eread,
                                                 const float* __restrict__ Wo,
                                                 const float* __restrict__ bo,
                                                 const float* __restrict__ Wl0,
                                                 const float* __restrict__ bl0,
                                                 const float* __restrict__ g0,
                                                 const float* __restrict__ b0) {
    extern __shared__ float sm[];
    float* sE  = sm;                   // logical-col E tile, stride 385
    float* seT = sE  + 32*SE_STR;      // e tile transposed, DOUBLE buffer [2][64][36]
    float* skn = seT + 2*SET_HALF;     // kn tile [jj][128], stride 132
    float* svn = skn + 32*KV_STR;      // vn tile
    float* sq  = svn + 32*KV_STR;      // q row (128); later: attnout row
    float* sf  = sq + 128;             // f per head [8][65]; later: st[128]+sred
    float* sp  = sf + 8*65;            // p per head [8][36]

    int b = blockIdx.x / NNODE, i = blockIdx.x % NNODE;
    int t = threadIdx.x, warp = t >> 5, lane = t & 31;
    int h = warp;  // 8 warps = 8 heads
    int dd = lane & 15, hi = lane >> 4;  // AV split: lane half 'hi' owns j-rows hi*16..

    // E-GEMM worker mapping: rows rh*16..+15, logical cols cb, cb+128, cb+256
    int rh = t >> 7, cb = t & 127;
    int ac0, ac1, ac2;
    {
        int L0 = cb, L1 = cb + 128, L2 = cb + 256;
        int w0 = L0 % 48, w1 = L1 % 48, w2 = L2 % 48;
        ac0 = (L0/48)*64 + (w0 < 32 ? w0 : w0 + 16);
        ac1 = (L1/48)*64 + (w1 < 32 ? w1 : w1 + 16);
        ac2 = (L2/48)*64 + (w2 < 32 ? w2 : w2 + 16);
    }

    if (t < DHv) { int hh = t >> 4, d = t & 15; sq[t] = g_qkvn[(b*NNODE + i)*384 + hh*48 + d]; }

    float m = -3.4e38f, lsum = 0.f, o = 0.f;
    float f0 = 0.f, f1 = 0.f;           // f cols: lane, lane+32
    const float* erow = eread + (size_t)(b*NNODE + i) * NNODE * DEv;

    // preload tile 0 into seT buffer 0
    for (int idx = t; idx < 32*64; idx += 256) {
        int jj = idx >> 6, c = idx & 63;
        seT[c*36 + jj] = erow[jj*DEv + c];
    }
    int cur = 0;

    for (int j0 = 0; j0 < NNODE; j0 += 32) {
        float* seTc = seT + cur*SET_HALF;
        float* seTn = seT + (cur^1)*SET_HALF;
        __syncthreads();  // prev tile readers done; seTc (stored last iter) visible
        // load kn, vn tiles (float4: 32 rows x 8 heads x 4 f4-units)
        #pragma unroll
        for (int u = 0; u < 4; u++) {
            int idx = t + u*256;
            int jj = idx >> 5, uu = idx & 31;
            int hh = uu >> 2, q4u = uu & 3;
            const float4* src = (const float4*)(g_qkvn + (size_t)(b*NNODE + j0 + jj)*384 + hh*48 + 16);
            ((float4*)(skn + jj*KV_STR + hh*16))[q4u] = __ldg(&src[q4u]);
            ((float4*)(svn + jj*KV_STR + hh*16))[q4u] = __ldg(&src[4 + q4u]);
        }
        // issue prefetch LDGs for next e tile (consumed after the GEMM)
        float pf[8];
        int jn = j0 + 32;
        if (jn < NNODE) {
            #pragma unroll
            for (int u = 0; u < 8; u++) {
                int idx = t + u*256;
                int jj = idx >> 6, c = idx & 63;
                pf[u] = __ldg(&erow[(jn + jj)*DEv + c]);
            }
        }
        __syncthreads();  // skn/svn ready
        // E = e_tile @ Wqkv_e[eq,ek,em]  (32 x 384): all 256 threads, 3 cols x 16 rows
        {
            u64t a0[8], a1[8], a2[8];
            #pragma unroll
            for (int q = 0; q < 8; q++) { a0[q] = 0ull; a1[q] = 0ull; a2[q] = 0ull; }
            #pragma unroll 4
            for (int k = 0; k < 64; k++) {
                u64t w0 = pack_ww(__ldg(&We[k*512 + ac0]));
                u64t w1 = pack_ww(__ldg(&We[k*512 + ac1]));
                u64t w2 = pack_ww(__ldg(&We[k*512 + ac2]));
                const float4* e4 = (const float4*)(seTc + k*36 + rh*16);
                #pragma unroll
                for (int q4 = 0; q4 < 4; q4++) {
                    F4u ev; ev.v = e4[q4];
                    ffma2(a0[q4*2],   ev.p[0], w0);
                    ffma2(a0[q4*2+1], ev.p[1], w0);
                    ffma2(a1[q4*2],   ev.p[0], w1);
                    ffma2(a1[q4*2+1], ev.p[1], w1);
                    ffma2(a2[q4*2],   ev.p[0], w2);
                    ffma2(a2[q4*2+1], ev.p[1], w2);
                }
            }
            #pragma unroll
            for (int q = 0; q < 8; q++) {
                int row = rh*16 + 2*q;
                U2u u0; u0.p = a0[q];
                sE[row*SE_STR + cb]       = u0.f[0];
                sE[(row+1)*SE_STR + cb]   = u0.f[1];
                U2u u1; u1.p = a1[q];
                sE[row*SE_STR + cb+128]     = u1.f[0];
                sE[(row+1)*SE_STR + cb+128] = u1.f[1];
                U2u u2; u2.p = a2[q];
                sE[row*SE_STR + cb+256]     = u2.f[0];
                sE[(row+1)*SE_STR + cb+256] = u2.f[1];
            }
        }
        // store prefetched next e tile into the other buffer (LDG latency now hidden)
        if (jn < NNODE) {
            #pragma unroll
            for (int u = 0; u < 8; u++) {
                int idx = t + u*256;
                int jj = idx >> 6, c = idx & 63;
                seTn[c*36 + jj] = pf[u];
            }
        }
        __syncthreads();  // sE ready
        // dots (lane = j within tile), online softmax per warp/head
        const float* Er = sE + lane*SE_STR + h*48;
        const float* kr = skn + lane*KV_STR + h*16;
        float dot = 0.f;
        #pragma unroll
        for (int d = 0; d < 16; d++)
            dot += (sq[h*16 + d] + Er[d]) * (kr[d] + Er[16 + d]);
        dot *= ATT_SCALE;
        float mt = dot;
        #pragma unroll
        for (int off = 16; off; off >>= 1) mt = fmaxf(mt, __shfl_xor_sync(0xffffffffu, mt, off));
        float mnew = fmaxf(m, mt);
        float p = expf(dot - mnew);
        float corr = expf(m - mnew);   // first tile: exp(-huge) = 0
        float ps = p;
        #pragma unroll
        for (int off = 16; off; off >>= 1) ps += __shfl_xor_sync(0xffffffffu, ps, off);
        lsum = lsum * corr + ps;
        o *= corr; f0 *= corr; f1 *= corr;
        // stage p for this warp's tile (own row; syncwarp is enough)
        sp[h*36 + lane] = p;
        __syncwarp();
        // f accumulation, float4 over j (seTc rows are j-contiguous)
        {
            const float4* pv4 = (const float4*)(sp + h*36);
            const float4* e0v = (const float4*)(seTc + lane*36);
            const float4* e1v = (const float4*)(seTc + (lane + 32)*36);
            #pragma unroll
            for (int jq = 0; jq < 8; jq++) {
                float4 pv = pv4[jq];
                float4 a = e0v[jq], bq = e1v[jq];
                f0 += pv.x*a.x + pv.y*a.y + pv.z*a.z + pv.w*a.w;
                f1 += pv.x*bq.x + pv.y*bq.y + pv.z*bq.z + pv.w*bq.w;
            }
        }
        // o[d] += sum_j p_j * vn[j,d]*em[j,d] — j split by lane-half
        #pragma unroll
        for (int jj = 0; jj < 16; jj++) {
            int jjj = hi*16 + jj;
            float pj = __shfl_sync(0xffffffffu, p, jjj);
            const float* Ej = sE + jjj*SE_STR + h*48;
            o += pj * (svn[jjj*KV_STR + h*16 + dd] * Ej[32 + dd]);
        }
        m = mnew;
        cur ^= 1;
    }
    // combine the two j-halves of o
    float of = o + __shfl_xor_sync(0xffffffffu, o, 16);
    // stash f for this head, then apply Wev projection (exact linear reorder)
    sf[h*65 + lane] = f0;
    sf[h*65 + 32 + lane] = f1;
    __syncwarp();
    float aout = 0.f;
    if (lane < 16) {
        float fv = 0.f;
        #pragma unroll 8
        for (int c = 0; c < 64; c++)
            fv += sf[h*65 + c] * __ldg(&We[c*512 + h*64 + 32 + lane]);
        aout = (of + fv) / lsum;
    }
    __syncthreads();            // sf readers done; repurpose sq/sf
    if (lane < 16) sq[h*16 + lane] = aout;   // sq := attnout row (128)
    float* st   = sf;           // st[128]
    float* sred = sf + 128;     // sred[10]
    __syncthreads();
    // ---- fused node1: x = ln(x + (attnout@Wo+bo)@Wl0 + bl0) ----
    int row = b*NNODE + i;
    if (t < DNv) {
        float acc = bo[t];
        #pragma unroll 16
        for (int k = 0; k < DHv; k++) acc += sq[k] * __ldg(&Wo[k*DNv + t]);
        st[t] = acc;
    }
    __syncthreads();
    float r = 0.f;
    if (t < DNv) {
        float u = bl0[t];
        #pragma unroll 16
        for (int k = 0; k < DNv; k++) u += st[k] * __ldg(&Wl0[k*DNv + t]);
        r = g_x[row*DNv + t] + u;
        float s = r, ss = r*r;
        #pragma unroll
        for (int off = 16; off; off >>= 1) {
            s  += __shfl_xor_sync(0xffffffffu, s, off);
            ss += __shfl_xor_sync(0xffffffffu, ss, off);
        }
        if (lane == 0) { sred[warp] = s; sred[4 + warp] = ss; }
    }
    __syncthreads();
    if (t == 0) {
        float S = sred[0]+sred[1]+sred[2]+sred[3];
        float SS = sred[4]+sred[5]+sred[6]+sred[7];
        float mean = S * (1.f/128.f);
        float var = SS * (1.f/128.f) - mean*mean;
        sred[8] = mean;
        sred[9] = rsqrtf(var + 1e-5f);
    }
    __syncthreads();
    if (t < DNv)
        g_x[row*DNv + t] = (r - sred[8]) * sred[9] * __ldg(&g0[t]) + __ldg(&b0[t]);
}

// ---------------- node MLP + srctgt + next qkvn (fused tails) ----------------
// x = ln(x + gelu(x@Wm1)@Wm2 + bm2); then src/tgt projections and next-layer
// qkv_n from the freshly computed x (column-parallel, no extra barriers).
__global__ void k_node2(const float* __restrict__ Wm1, const float* __restrict__ Wm2,
                        const float* __restrict__ bm2,
                        const float* __restrict__ gam, const float* __restrict__ bet,
                        float* __restrict__ xout, int wout,
                        const float* __restrict__ Ws, const float* __restrict__ bs,
                        const float* __restrict__ Wt, const float* __restrict__ bt,
                        const float* __restrict__ Wqn, int do_qkv) {
    __shared__ float sx[DNv];
    __shared__ float sh[DNHv];
    __shared__ float sred[10];
    int row = blockIdx.x; int t = threadIdx.x;  // 128 threads
    int warp = t >> 5, lane = t & 31;
    float xv = g_x[row*DNv + t];
    sx[t] = xv;
    __syncthreads();
    for (int c = t; c < DNHv; c += 128) {
        float acc = 0.f;
        #pragma unroll 16
        for (int k = 0; k < DNv; k++) acc += sx[k] * __ldg(&Wm1[k*DNHv + c]);
        sh[c] = gelu_f(acc);
    }
    __syncthreads();
    float u = bm2[t];
    #pragma unroll 16
    for (int k = 0; k < DNHv; k++) u += sh[k] * __ldg(&Wm2[k*DNv + t]);
    float r = xv + u;
    // inline LN (128 threads)
    {
        float s = r, ss = r*r;
        #pragma unroll
        for (int off = 16; off; off >>= 1) {
            s  += __shfl_xor_sync(0xffffffffu, s, off);
            ss += __shfl_xor_sync(0xffffffffu, ss, off);
        }
        if (lane == 0) { sred[warp] = s; sred[4 + warp] = ss; }
    }
    __syncthreads();
    if (t == 0) {
        float S = sred[0]+sred[1]+sred[2]+sred[3];
        float SS = sred[4]+sred[5]+sred[6]+sred[7];
        float mean = S * (1.f/128.f);
        float var = SS * (1.f/128.f) - mean*mean;
        sred[8] = mean;
        sred[9] = rsqrtf(var + 1e-5f);
    }
    __syncthreads();
    float y = (r - sred[8]) * sred[9] * gam[t] + bet[t];
    g_x[row*DNv + t] = y;
    if (wout) xout[row*DNv + t] = y;
    sx[t] = y;                 // sx := post-LN x
    __syncthreads();
    // ---- fused srctgt (2 cols/thread) ----
    #pragma unroll
    for (int half = 0; half < 2; half++) {
        int c = t + half*128;
        float a = bs[c], c2 = bt[c];
        #pragma unroll 16
        for (int k = 0; k < DNv; k++) {
            float x2 = sx[k];
            a  += x2 * __ldg(&Ws[k*DEHv + c]);
            c2 += x2 * __ldg(&Wt[k*DEHv + c]);
        }
        g_src[row*DEHv + c] = a;
        g_tgt[row*DEHv + c] = c2;
    }
    // ---- fused next-layer qkv_n ----
    if (do_qkv) {
        for (int c = t; c < 3*DHv; c += 128) {
            float acc = 0.f;
            #pragma unroll 16
            for (int k = 0; k < DNv; k++) acc += sx[k] * __ldg(&Wqn[k*384 + c]);
            g_qkvn[row*384 + c] = acc;
        }
    }
}

// ---------------- fused edge update kernel -----------------------------------
// block = (b, i, j-tile of 32), 256 threads.  r2 aliases stT (disjoint lifetimes)
#define SMEM_EDGE ((128*36 + 256*36 + 2048 + 64*36 + 256) * 4)
__global__ void __launch_bounds__(256, 3) k_edge(
                       const float* __restrict__ We0, const float* __restrict__ be0,
                       const float* __restrict__ We1, const float* __restrict__ be1,
                       const float* __restrict__ g0, const float* __restrict__ b0,
                       const float* __restrict__ Wem1, const float* __restrict__ Wem2,
                       const float* __restrict__ bem2,
                       const float* __restrict__ g1, const float* __restrict__ b1,
                       const float* __restrict__ eread, float* __restrict__ ewrite) {
    extern __shared__ float sm[];
    float* secatT = sm;                 // [k=128][jj=32] stride 36
    float* shT    = secatT + 128*36;    // [k=256][jj=32] stride 36
    float* stRM   = shT + 256*36;       // [jj=32][c=64] row-major
    float* stT    = stRM + 2048;        // [k=64][jj=32] stride 36
    float* r2     = stT;                // ALIAS: r2 live only after stT is dead
    float* ssrc   = stT + 64*36;        // 256

    int jt = blockIdx.x & 7;
    int bi = blockIdx.x >> 3;           // b*N+i
    int b = bi >> 8, i = bi & 255;
    int j0 = jt * 32;
    int t = threadIdx.x;

    // load ecat = [e_ij, e_ji] transposed
    for (int idx = t; idx < 32*64; idx += 256) {
        int jj = idx >> 6, c = idx & 63;
        secatT[c*36 + jj]        = eread[((size_t)bi*NNODE + j0 + jj)*DEv + c];
        secatT[(64 + c)*36 + jj] = eread[((size_t)(b*NNODE + j0 + jj)*NNODE + i)*DEv + c];
    }
    ssrc[t] = g_src[(size_t)bi*DEHv + t];
    __syncthreads();

    // h = gelu(ecat @ We0 + be0 + src_i + tgt_j)   (32 x 256), C=2 cols x 16 rows
    {
        int c = t & 127;     // cols c and c+128
        int jg = t >> 7;     // row-half: rows jg*16 .. jg*16+15
        u64t acc0[8], acc1[8];
        u64t init0 = pack_ww(__ldg(&be0[c])       + ssrc[c]);
        u64t init1 = pack_ww(__ldg(&be0[c + 128]) + ssrc[c + 128]);
        #pragma unroll
        for (int q = 0; q < 8; q++) { acc0[q] = init0; acc1[q] = init1; }
        #pragma unroll 4
        for (int k = 0; k < 128; k++) {
            u64t w0 = pack_ww(__ldg(&We0[k*DEHv + c]));
            u64t w1 = pack_ww(__ldg(&We0[k*DEHv + c + 128]));
            const float4* e4 = (const float4*)(secatT + k*36 + jg*16);
            #pragma unroll
            for (int q4 = 0; q4 < 4; q4++) {
                F4u ev; ev.v = e4[q4];
                ffma2(acc0[q4*2],   ev.p[0], w0);
                ffma2(acc0[q4*2+1], ev.p[1], w0);
                ffma2(acc1[q4*2],   ev.p[0], w1);
                ffma2(acc1[q4*2+1], ev.p[1], w1);
            }
        }
        #pragma unroll
        for (int q = 0; q < 8; q++) {
            int jj = jg*16 + 2*q;
            size_t tb0 = (size_t)(b*NNODE + j0 + jj)*DEHv;
            size_t tb1 = (size_t)(b*NNODE + j0 + jj + 1)*DEHv;
            U2u u0; u0.p = acc0[q];
            shT[c*36 + jj]     = gelu_f(u0.f[0] + __ldg(&g_tgt[tb0 + c]));
            shT[c*36 + jj + 1] = gelu_f(u0.f[1] + __ldg(&g_tgt[tb1 + c]));
            U2u u1; u1.p = acc1[q];
            shT[(c+128)*36 + jj]     = gelu_f(u1.f[0] + __ldg(&g_tgt[tb0 + c + 128]));
            shT[(c+128)*36 + jj + 1] = gelu_f(u1.f[1] + __ldg(&g_tgt[tb1 + c + 128]));
        }
    }
    __syncthreads();

    // e_pre = e + h @ We1 + be1  (32 x 64), K-split 2 x row-split 2 (R=16)
    {
        int c = t & 63, g = t >> 6;
        int rh = g & 1, kg = g >> 1;
        u64t acc[8];
        #pragma unroll
        for (int n = 0; n < 8; n++) acc[n] = 0ull;
        int kbeg = kg*128;
        #pragma unroll 8
        for (int kk = 0; kk < 128; kk++) {
            int k = kbeg + kk;
            u64t ww = pack_ww(__ldg(&We1[k*64 + c]));
            const float4* h4 = (const float4*)(shT + k*36 + rh*16);
            F4u a0, a1, a2, a3; a0.v = h4[0]; a1.v = h4[1]; a2.v = h4[2]; a3.v = h4[3];
            ffma2(acc[0], a0.p[0], ww); ffma2(acc[1], a0.p[1], ww);
            ffma2(acc[2], a1.p[0], ww); ffma2(acc[3], a1.p[1], ww);
            ffma2(acc[4], a2.p[0], ww); ffma2(acc[5], a2.p[1], ww);
            ffma2(acc[6], a3.p[0], ww); ffma2(acc[7], a3.p[1], ww);
        }
        u64t* scr = (u64t*)stT;  // stT not yet written; free as scratch
        if (kg == 1) {
            #pragma unroll
            for (int n = 0; n < 8; n++) scr[(n*2 + rh)*64 + c] = acc[n];
        }
        __syncthreads();
        if (kg == 0) {
            float bb1 = __ldg(&be1[c]);
            #pragma unroll
            for (int n = 0; n < 8; n++) {
                U2u u; u.p = acc[n];
                U2u v; v.p = scr[(n*2 + rh)*64 + c];
                int jj = rh*16 + 2*n;
                stRM[jj*64 + c]     = u.f[0] + v.f[0] + bb1 + eread[((size_t)bi*NNODE + j0 + jj)*DEv + c];
                stRM[(jj+1)*64 + c] = u.f[1] + v.f[1] + bb1 + eread[((size_t)bi*NNODE + j0 + jj + 1)*DEv + c];
            }
        }
    }
    __syncthreads();

    // LN0 per 64-wide row -> stRM (normalized) and stT (transposed)
    {
        int warp = t >> 5, lane = t & 31;
        for (int r = warp; r < 32; r += 8) {
            float a = stRM[r*64 + lane], q = stRM[r*64 + 32 + lane];
            float s = a + q, ss = a*a + q*q;
            #pragma unroll
            for (int off = 16; off; off >>= 1) {
                s  += __shfl_xor_sync(0xffffffffu, s, off);
                ss += __shfl_xor_sync(0xffffffffu, ss, off);
            }
            float mean = s * (1.f/64.f);
            float var = ss * (1.f/64.f) - mean*mean;
            float rstd = rsqrtf(var + 1e-5f);
            float y0 = (a - mean)*rstd*__ldg(&g0[lane])      + __ldg(&b0[lane]);
            float y1 = (q - mean)*rstd*__ldg(&g0[lane + 32]) + __ldg(&b0[lane + 32]);
            stRM[r*64 + lane] = y0; stRM[r*64 + 32 + lane] = y1;
            stT[lane*36 + r] = y0; stT[(lane + 32)*36 + r] = y1;
        }
    }
    __syncthreads();

    // hidden2 = gelu(e_new @ Wem1)   (32 x 256), reuse shT; C=2 cols x 16 rows
    {
        int c = t & 127;
        int jg = t >> 7;
        u64t acc0[8], acc1[8];
        #pragma unroll
        for (int q = 0; q < 8; q++) { acc0[q] = 0ull; acc1[q] = 0ull; }
        #pragma unroll 4
        for (int k = 0; k < 64; k++) {
            u64t w0 = pack_ww(__ldg(&Wem1[k*DEHv + c]));
            u64t w1 = pack_ww(__ldg(&Wem1[k*DEHv + c + 128]));
            const float4* e4 = (const float4*)(stT + k*36 + jg*16);
            #pragma unroll
            for (int q4 = 0; q4 < 4; q4++) {
                F4u ev; ev.v = e4[q4];
                ffma2(acc0[q4*2],   ev.p[0], w0);
                ffma2(acc0[q4*2+1], ev.p[1], w0);
                ffma2(acc1[q4*2],   ev.p[0], w1);
                ffma2(acc1[q4*2+1], ev.p[1], w1);
            }
        }
        #pragma unroll
        for (int q = 0; q < 8; q++) {
            int jj = jg*16 + 2*q;
            U2u u0; u0.p = acc0[q];
            shT[c*36 + jj]     = gelu_f(u0.f[0]);
            shT[c*36 + jj + 1] = gelu_f(u0.f[1]);
            U2u u1; u1.p = acc1[q];
            shT[(c+128)*36 + jj]     = gelu_f(u1.f[0]);
            shT[(c+128)*36 + jj + 1] = gelu_f(u1.f[1]);
        }
    }
    __syncthreads();

    // r2 = e_new + hidden2 @ Wem2 + bem2  (32 x 64), K-split 2 x row-split 2
    {
        int c = t & 63, g = t >> 6;
        int rh = g & 1, kg = g >> 1;
        u64t acc[8];
        #pragma unroll
        for (int n = 0; n < 8; n++) acc[n] = 0ull;
        int kbeg = kg*128;
        #pragma unroll 8
        for (int kk = 0; kk < 128; kk++) {
            int k = kbeg + kk;
            u64t ww = pack_ww(__ldg(&Wem2[k*64 + c]));
            const float4* h4 = (const float4*)(shT + k*36 + rh*16);
            F4u a0, a1, a2, a3; a0.v = h4[0]; a1.v = h4[1]; a2.v = h4[2]; a3.v = h4[3];
            ffma2(acc[0], a0.p[0], ww); ffma2(acc[1], a0.p[1], ww);
            ffma2(acc[2], a1.p[0], ww); ffma2(acc[3], a1.p[1], ww);
            ffma2(acc[4], a2.p[0], ww); ffma2(acc[5], a2.p[1], ww);
            ffma2(acc[6], a3.p[0], ww); ffma2(acc[7], a3.p[1], ww);
        }
        u64t* scr = (u64t*)secatT;  // secatT free at this stage
        if (kg == 1) {
            #pragma unroll
            for (int n = 0; n < 8; n++) scr[(n*2 + rh)*64 + c] = acc[n];
        }
        __syncthreads();
        if (kg == 0) {
            float bb2 = __ldg(&bem2[c]);
            #pragma unroll
            for (int n = 0; n < 8; n++) {
                U2u u; u.p = acc[n];
                U2u v; v.p = scr[(n*2 + rh)*64 + c];
                int jj = rh*16 + 2*n;
                r2[jj*64 + c]     = u.f[0] + v.f[0] + bb2 + stRM[jj*64 + c];
                r2[(jj+1)*64 + c] = u.f[1] + v.f[1] + bb2 + stRM[(jj+1)*64 + c];
            }
        }
    }
    __syncthreads();

    // LN1 per row -> write out
    {
        int warp = t >> 5, lane = t & 31;
        for (int r = warp; r < 32; r += 8) {
            float a = r2[r*64 + lane], q = r2[r*64 + 32 + lane];
            float s = a + q, ss = a*a + q*q;
            #pragma unroll
            for (int off = 16; off; off >>= 1) {
                s  += __shfl_xor_sync(0xffffffffu, s, off);
                ss += __shfl_xor_sync(0xffffffffu, ss, off);
            }
            float mean = s * (1.f/64.f);
            float var = ss * (1.f/64.f) - mean*mean;
            float rstd = rsqrtf(var + 1e-5f);
            float y0 = (a - mean)*rstd*__ldg(&g1[lane])      + __ldg(&b1[lane]);
            float y1 = (q - mean)*rstd*__ldg(&g1[lane + 32]) + __ldg(&b1[lane + 32]);
            size_t orow = ((size_t)bi*NNODE + j0 + r)*DEv;
            ewrite[orow + lane] = y0;
            ewrite[orow + 32 + lane] = y1;
        }
    }
}

// ---------------- host launcher ----------------------------------------------
extern "C" void kernel_launch(void* const* d_in, const int* in_sizes, int n_in,
                              void* d_out, int out_size) {
    const float* node   = (const float*)d_in[0];
    const float* edge   = (const float*)d_in[1];
    const float* Wqkv_n = (const float*)d_in[2];
    const float* Wqkv_e = (const float*)d_in[3];
    const float* Wo     = (const float*)d_in[4];
    const float* bo     = (const float*)d_in[5];
    const float* Wl0    = (const float*)d_in[6];
    const float* bl0    = (const float*)d_in[7];
    const float* ln0_g  = (const float*)d_in[8];
    const float* ln0_b  = (const float*)d_in[9];
    const float* Wm1    = (const float*)d_in[10];
    const float* Wm2    = (const float*)d_in[11];
    const float* bm2    = (const float*)d_in[12];
    const float* ln1_g  = (const float*)d_in[13];
    const float* ln1_b  = (const float*)d_in[14];
    const float* We0    = (const float*)d_in[15];
    const float* be0    = (const float*)d_in[16];
    const float* Ws     = (const float*)d_in[17];
    const float* bs     = (const float*)d_in[18];
    const float* Wt     = (const float*)d_in[19];
    const float* bt     = (const float*)d_in[20];
    const float* We1    = (const float*)d_in[21];
    const float* be1    = (const float*)d_in[22];
    const float* eln0_g = (const float*)d_in[23];
    const float* eln0_b = (const float*)d_in[24];
    const float* Wem1   = (const float*)d_in[25];
    const float* Wem2   = (const float*)d_in[26];
    const float* bem2   = (const float*)d_in[27];
    const float* eln1_g = (const float*)d_in[28];
    const float* eln1_b = (const float*)d_in[29];
    float* out = (float*)d_out;

    cudaFuncSetAttribute(k_attn, cudaFuncAttributeMaxDynamicSharedMemorySize, SMEM_ATTN);
    cudaFuncSetAttribute(k_edge, cudaFuncAttributeMaxDynamicSharedMemorySize, SMEM_EDGE);

    float* ebuf = nullptr;
    cudaGetSymbolAddress((void**)&ebuf, g_ebuf);
    float* out_e = out + BB*NNODE*DNv;   // e region of d_out

    k_copy_in<<<64, 256>>>((const float4*)node);
    k_qkvn<<<BB*NNODE, 128>>>(Wqkv_n);  // layer 0 qkv

    for (int l = 0; l < NLAYER; l++) {
        int has_next = (l + 1 < NLAYER);
        int ln = has_next ? l + 1 : l;
        // e buffer chain: input edge -> g_ebuf -> d_out e-region
        const float* eread = (l == 0) ? edge : ebuf;
        float* ewrite = has_next ? ebuf : out_e;
        k_attn<<<BB*NNODE, 256, SMEM_ATTN>>>(Wqkv_e + (size_t)l*DEv*4*DHv, eread,
                                             Wo + (size_t)l*DHv*DNv, bo + l*DNv,
                                             Wl0 + (size_t)l*DNv*DNv, bl0 + l*DNv,
                                             ln0_g + l*DNv, ln0_b + l*DNv);
        k_node2<<<BB*NNODE, 128>>>(Wm1 + (size_t)l*DNv*DNHv, Wm2 + (size_t)l*DNHv*DNv,
                                   bm2 + l*DNv, ln1_g + l*DNv, ln1_b + l*DNv,
                                   out, has_next ? 0 : 1,
                                   Ws + (size_t)l*DNv*DEHv, bs + l*DEHv,
                                   Wt + (size_t)l*DNv*DEHv, bt + l*DEHv,
                                   Wqkv_n + (size_t)ln*DNv*3*DHv, has_next);
        k_edge<<<BB*NNODE*8, 256, SMEM_EDGE>>>(
            We0 + (size_t)l*2*DEv*DEHv, be0 + l*DEHv,
            We1 + (size_t)l*DEHv*DEv,  be1 + l*DEv,
            eln0_g + l*DEv, eln0_b + l*DEv,
            Wem1 + (size_t)l*DEv*DEHv, Wem2 + (size_t)l*DEHv*DEv,
            bem2 + l*DEv, eln1_g + l*DEv, eln1_b + l*DEv,
            eread, ewrite);
    }
}

// round 15
// speedup vs baseline: 1.0627x; 1.0257x over previous
#include <cuda_runtime.h>
#include <math.h>

// dims
#define BB   2
#define NNODE 256
#define DNv  128
#define DEv  64
#define DHv  128
#define Hh   8
#define DHHv 16
#define DNHv 512
#define DEHv 256
#define NLAYER 2
#define ATT_SCALE 0.088388347648318447f  // 1/sqrt(128)

typedef unsigned long long u64t;

// packed fp32x2 FMA (Blackwell): one issue slot, two fp32 FMAs, exact .rn numerics
__device__ __forceinline__ void ffma2(u64t& acc, u64t a, u64t b) {
    asm("fma.rn.f32x2 %0, %1, %2, %0;" : "+l"(acc) : "l"(a), "l"(b));
}
__device__ __forceinline__ u64t pack_ww(float w) {
    u64t r; asm("mov.b64 %0, {%1, %1};" : "=l"(r) : "f"(w)); return r;
}
union F4u { float4 v; u64t p[2]; };
union U2u { u64t p; float f[2]; };

// ---------------- scratch (device globals; no allocations allowed) ----------
__device__ float g_x[BB*NNODE*DNv];
__device__ float g_ebuf[BB*NNODE*NNODE*DEv];   // intermediate e (after layer 0)
__device__ float g_qkvn[BB*NNODE*3*DHv];
__device__ float g_src[BB*NNODE*DEHv];
__device__ float g_tgt[BB*NNODE*DEHv];

__device__ __forceinline__ float gelu_f(float x) {
    return 0.5f * x * (1.0f + erff(x * 0.70710678118654752440f));
}

// ---------------- copy in: node features only --------------------------------
__global__ void k_copy_in(const float4* __restrict__ node) {
    int tid = blockIdx.x * blockDim.x + threadIdx.x;
    float4* x4 = (float4*)g_x;
    if (tid < BB*NNODE*DNv/4) x4[tid] = node[tid];
}

// ---------------- qkv_n for layer 0 only -------------------------------------
__global__ void k_qkvn(const float* __restrict__ W) {  // W: [128][384]
    __shared__ float sx[DNv];
    int row = blockIdx.x;
    int t = threadIdx.x;   // 128 threads
    sx[t] = g_x[row*DNv + t];
    __syncthreads();
    for (int c = t; c < 3*DHv; c += 128) {
        float acc = 0.f;
        #pragma unroll 16
        for (int k = 0; k < DNv; k++) acc += sx[k] * __ldg(&W[k*384 + c]);
        g_qkvn[row*384 + c] = acc;
    }
}

// ---------------- fused attention + node1: per (b,i) -------------------------
// R12 structure (occ 2, double-buffered seT prefetch) + fused node1 epilogue:
// x = ln(x + (attnout@Wo+bo)@Wl0 + bl0) computed in-block (row fully owned).
#define SE_STR 385
#define KV_STR 132
#define SET_HALF (64*36)
#define SMEM_ATTN ((32*SE_STR + 2*SET_HALF + 32*KV_STR + 32*KV_STR + 128 + 8*65 + 8*36) * 4)
__global__ void __launch_bounds__(256, 2) k_attn(const float* __restrict__ We,
                                                 const float* __restrict__ eread,
                                                 const float* __restrict__ Wo,
                                                 const float* __restrict__ bo,
                                                 const float* __restrict__ Wl0,
                                                 const float* __restrict__ bl0,
                                                 const float* __restrict__ g0,
                                                 const float* __restrict__ b0) {
    extern __shared__ float sm[];
    float* sE  = sm;                   // logical-col E tile, stride 385
    float* seT = sE  + 32*SE_STR;      // e tile transposed, DOUBLE buffer [2][64][36]
    float* skn = seT + 2*SET_HALF;     // kn tile [jj][128], stride 132
    float* svn = skn + 32*KV_STR;      // vn tile
    float* sq  = svn + 32*KV_STR;      // q row (128); later: attnout row
    float* sf  = sq + 128;             // f per head [8][65]; later: st[128]+sred
    float* sp  = sf + 8*65;            // p per head [8][36]

    int b = blockIdx.x / NNODE, i = blockIdx.x % NNODE;
    int t = threadIdx.x, warp = t >> 5, lane = t & 31;
    int h = warp;  // 8 warps = 8 heads
    int dd = lane & 15, hi = lane >> 4;  // AV split: lane half 'hi' owns j-rows hi*16..

    // E-GEMM worker mapping: rows rh*16..+15, logical cols cb, cb+128, cb+256
    int rh = t >> 7, cb = t & 127;
    int ac0, ac1, ac2;
    {
        int L0 = cb, L1 = cb + 128, L2 = cb + 256;
        int w0 = L0 % 48, w1 = L1 % 48, w2 = L2 % 48;
        ac0 = (L0/48)*64 + (w0 < 32 ? w0 : w0 + 16);
        ac1 = (L1/48)*64 + (w1 < 32 ? w1 : w1 + 16);
        ac2 = (L2/48)*64 + (w2 < 32 ? w2 : w2 + 16);
    }

    if (t < DHv) { int hh = t >> 4, d = t & 15; sq[t] = g_qkvn[(b*NNODE + i)*384 + hh*48 + d]; }

    float m = -3.4e38f, lsum = 0.f, o = 0.f;
    float f0 = 0.f, f1 = 0.f;           // f cols: lane, lane+32
    const float* erow = eread + (size_t)(b*NNODE + i) * NNODE * DEv;

    // preload tile 0 into seT buffer 0
    for (int idx = t; idx < 32*64; idx += 256) {
        int jj = idx >> 6, c = idx & 63;
        seT[c*36 + jj] = erow[jj*DEv + c];
    }
    int cur = 0;

    for (int j0 = 0; j0 < NNODE; j0 += 32) {
        float* seTc = seT + cur*SET_HALF;
        float* seTn = seT + (cur^1)*SET_HALF;
        __syncthreads();  // prev tile readers done; seTc (stored last iter) visible
        // load kn, vn tiles (float4: 32 rows x 8 heads x 4 f4-units)
        #pragma unroll
        for (int u = 0; u < 4; u++) {
            int idx = t + u*256;
            int jj = idx >> 5, uu = idx & 31;
            int hh = uu >> 2, q4u = uu & 3;
            const float4* src = (const float4*)(g_qkvn + (size_t)(b*NNODE + j0 + jj)*384 + hh*48 + 16);
            ((float4*)(skn + jj*KV_STR + hh*16))[q4u] = __ldg(&src[q4u]);
            ((float4*)(svn + jj*KV_STR + hh*16))[q4u] = __ldg(&src[4 + q4u]);
        }
        // issue prefetch LDGs for next e tile (consumed after the GEMM)
        float pf[8];
        int jn = j0 + 32;
        if (jn < NNODE) {
            #pragma unroll
            for (int u = 0; u < 8; u++) {
                int idx = t + u*256;
                int jj = idx >> 6, c = idx & 63;
                pf[u] = __ldg(&erow[(jn + jj)*DEv + c]);
            }
        }
        __syncthreads();  // skn/svn ready
        // E = e_tile @ Wqkv_e[eq,ek,em]  (32 x 384): all 256 threads, 3 cols x 16 rows
        {
            u64t a0[8], a1[8], a2[8];
            #pragma unroll
            for (int q = 0; q < 8; q++) { a0[q] = 0ull; a1[q] = 0ull; a2[q] = 0ull; }
            #pragma unroll 4
            for (int k = 0; k < 64; k++) {
                u64t w0 = pack_ww(__ldg(&We[k*512 + ac0]));
                u64t w1 = pack_ww(__ldg(&We[k*512 + ac1]));
                u64t w2 = pack_ww(__ldg(&We[k*512 + ac2]));
                const float4* e4 = (const float4*)(seTc + k*36 + rh*16);
                #pragma unroll
                for (int q4 = 0; q4 < 4; q4++) {
                    F4u ev; ev.v = e4[q4];
                    ffma2(a0[q4*2],   ev.p[0], w0);
                    ffma2(a0[q4*2+1], ev.p[1], w0);
                    ffma2(a1[q4*2],   ev.p[0], w1);
                    ffma2(a1[q4*2+1], ev.p[1], w1);
                    ffma2(a2[q4*2],   ev.p[0], w2);
                    ffma2(a2[q4*2+1], ev.p[1], w2);
                }
            }
            #pragma unroll
            for (int q = 0; q < 8; q++) {
                int row = rh*16 + 2*q;
                U2u u0; u0.p = a0[q];
                sE[row*SE_STR + cb]       = u0.f[0];
                sE[(row+1)*SE_STR + cb]   = u0.f[1];
                U2u u1; u1.p = a1[q];
                sE[row*SE_STR + cb+128]     = u1.f[0];
                sE[(row+1)*SE_STR + cb+128] = u1.f[1];
                U2u u2; u2.p = a2[q];
                sE[row*SE_STR + cb+256]     = u2.f[0];
                sE[(row+1)*SE_STR + cb+256] = u2.f[1];
            }
        }
        // store prefetched next e tile into the other buffer (LDG latency now hidden)
        if (jn < NNODE) {
            #pragma unroll
            for (int u = 0; u < 8; u++) {
                int idx = t + u*256;
                int jj = idx >> 6, c = idx & 63;
                seTn[c*36 + jj] = pf[u];
            }
        }
        __syncthreads();  // sE ready
        // dots (lane = j within tile), online softmax per warp/head
        const float* Er = sE + lane*SE_STR + h*48;
        const float* kr = skn + lane*KV_STR + h*16;
        float dot = 0.f;
        #pragma unroll
        for (int d = 0; d < 16; d++)
            dot += (sq[h*16 + d] + Er[d]) * (kr[d] + Er[16 + d]);
        dot *= ATT_SCALE;
        float mt = dot;
        #pragma unroll
        for (int off = 16; off; off >>= 1) mt = fmaxf(mt, __shfl_xor_sync(0xffffffffu, mt, off));
        float mnew = fmaxf(m, mt);
        float p = expf(dot - mnew);
        float corr = expf(m - mnew);   // first tile: exp(-huge) = 0
        float ps = p;
        #pragma unroll
        for (int off = 16; off; off >>= 1) ps += __shfl_xor_sync(0xffffffffu, ps, off);
        lsum = lsum * corr + ps;
        o *= corr; f0 *= corr; f1 *= corr;
        // stage p for this warp's tile (own row; syncwarp is enough)
        sp[h*36 + lane] = p;
        __syncwarp();
        // f accumulation, float4 over j (seTc rows are j-contiguous)
        {
            const float4* pv4 = (const float4*)(sp + h*36);
            const float4* e0v = (const float4*)(seTc + lane*36);
            const float4* e1v = (const float4*)(seTc + (lane + 32)*36);
            #pragma unroll
            for (int jq = 0; jq < 8; jq++) {
                float4 pv = pv4[jq];
                float4 a = e0v[jq], bq = e1v[jq];
                f0 += pv.x*a.x + pv.y*a.y + pv.z*a.z + pv.w*a.w;
                f1 += pv.x*bq.x + pv.y*bq.y + pv.z*bq.z + pv.w*bq.w;
            }
        }
        // o[d] += sum_j p_j * vn[j,d]*em[j,d] — j split by lane-half
        #pragma unroll
        for (int jj = 0; jj < 16; jj++) {
            int jjj = hi*16 + jj;
            float pj = __shfl_sync(0xffffffffu, p, jjj);
            const float* Ej = sE + jjj*SE_STR + h*48;
            o += pj * (svn[jjj*KV_STR + h*16 + dd] * Ej[32 + dd]);
        }
        m = mnew;
        cur ^= 1;
    }
    // combine the two j-halves of o
    float of = o + __shfl_xor_sync(0xffffffffu, o, 16);
    // stash f for this head, then apply Wev projection (exact linear reorder)
    sf[h*65 + lane] = f0;
    sf[h*65 + 32 + lane] = f1;
    __syncwarp();
    float aout = 0.f;
    if (lane < 16) {
        float fv = 0.f;
        #pragma unroll 8
        for (int c = 0; c < 64; c++)
            fv += sf[h*65 + c] * __ldg(&We[c*512 + h*64 + 32 + lane]);
        aout = (of + fv) / lsum;
    }
    __syncthreads();            // sf readers done; repurpose sq/sf
    if (lane < 16) sq[h*16 + lane] = aout;   // sq := attnout row (128)
    float* st   = sf;           // st[128]
    float* sred = sf + 128;     // sred[10]
    __syncthreads();
    // ---- fused node1: x = ln(x + (attnout@Wo+bo)@Wl0 + bl0) ----
    int row = b*NNODE + i;
    if (t < DNv) {
        float acc = bo[t];
        #pragma unroll 16
        for (int k = 0; k < DHv; k++) acc += sq[k] * __ldg(&Wo[k*DNv + t]);
        st[t] = acc;
    }
    __syncthreads();
    float r = 0.f;
    if (t < DNv) {
        float u = bl0[t];
        #pragma unroll 16
        for (int k = 0; k < DNv; k++) u += st[k] * __ldg(&Wl0[k*DNv + t]);
        r = g_x[row*DNv + t] + u;
        float s = r, ss = r*r;
        #pragma unroll
        for (int off = 16; off; off >>= 1) {
            s  += __shfl_xor_sync(0xffffffffu, s, off);
            ss += __shfl_xor_sync(0xffffffffu, ss, off);
        }
        if (lane == 0) { sred[warp] = s; sred[4 + warp] = ss; }
    }
    __syncthreads();
    if (t == 0) {
        float S = sred[0]+sred[1]+sred[2]+sred[3];
        float SS = sred[4]+sred[5]+sred[6]+sred[7];
        float mean = S * (1.f/128.f);
        float var = SS * (1.f/128.f) - mean*mean;
        sred[8] = mean;
        sred[9] = rsqrtf(var + 1e-5f);
    }
    __syncthreads();
    if (t < DNv)
        g_x[row*DNv + t] = (r - sred[8]) * sred[9] * __ldg(&g0[t]) + __ldg(&b0[t]);
}

// ---------------- LayerNorm helper for 128-wide rows (128 threads) -----------
__device__ __forceinline__ float ln128(float r, const float* __restrict__ g,
                                       const float* __restrict__ bta, float* sred, int t) {
    __syncthreads();  // protect sred reuse
    int warp = t >> 5, lane = t & 31;
    float s = r, ss = r*r;
    #pragma unroll
    for (int off = 16; off; off >>= 1) {
        s  += __shfl_xor_sync(0xffffffffu, s, off);
        ss += __shfl_xor_sync(0xffffffffu, ss, off);
    }
    if (lane == 0) { sred[warp] = s; sred[4 + warp] = ss; }
    __syncthreads();
    if (t == 0) {
        float S = sred[0]+sred[1]+sred[2]+sred[3];
        float SS = sred[4]+sred[5]+sred[6]+sred[7];
        float mean = S * (1.f/128.f);
        float var = SS * (1.f/128.f) - mean*mean;
        sred[8] = mean;
        sred[9] = rsqrtf(var + 1e-5f);
    }
    __syncthreads();
    return (r - sred[8]) * sred[9] * g[t] + bta[t];
}

// ---------------- node MLP: x = ln(x + gelu(x@Wm1)@Wm2 + bm2) ----------------
// wout: also write final x into xout (d_out) on the last layer
__global__ void k_node2(const float* __restrict__ Wm1, const float* __restrict__ Wm2,
                        const float* __restrict__ bm2,
                        const float* __restrict__ gam, const float* __restrict__ bet,
                        float* __restrict__ xout, int wout) {
    __shared__ float sx[DNv];
    __shared__ float sh[DNHv];
    __shared__ float sred[10];
    int row = blockIdx.x; int t = threadIdx.x;
    float xv = g_x[row*DNv + t];
    sx[t] = xv;
    __syncthreads();
    for (int c = t; c < DNHv; c += 128) {
        float acc = 0.f;
        #pragma unroll 16
        for (int k = 0; k < DNv; k++) acc += sx[k] * __ldg(&Wm1[k*DNHv + c]);
        sh[c] = gelu_f(acc);
    }
    __syncthreads();
    float u = bm2[t];
    #pragma unroll 16
    for (int k = 0; k < DNHv; k++) u += sh[k] * __ldg(&Wm2[k*DNv + t]);
    float r = xv + u;
    float y = ln128(r, gam, bet, sred, t);
    g_x[row*DNv + t] = y;
    if (wout) xout[row*DNv + t] = y;
}

// ---------------- aux: srctgt (blocks 0..511) + next-layer qkvn (512..1023) --
__global__ void k_aux(const float* __restrict__ Ws, const float* __restrict__ bs,
                      const float* __restrict__ Wt, const float* __restrict__ bt,
                      const float* __restrict__ Wqn, int do_qkv) {
    __shared__ float sx[DNv];
    int t = threadIdx.x;  // 256 threads
    if (blockIdx.x < BB*NNODE) {
        int row = blockIdx.x;
        if (t < DNv) sx[t] = g_x[row*DNv + t];
        __syncthreads();
        float a = bs[t], c2 = bt[t];
        #pragma unroll 16
        for (int k = 0; k < DNv; k++) {
            float xv = sx[k];
            a  += xv * __ldg(&Ws[k*DEHv + t]);
            c2 += xv * __ldg(&Wt[k*DEHv + t]);
        }
        g_src[row*DEHv + t] = a;
        g_tgt[row*DEHv + t] = c2;
    } else {
        if (!do_qkv) return;
        int row = blockIdx.x - BB*NNODE;
        if (t < DNv) sx[t] = g_x[row*DNv + t];
        __syncthreads();
        for (int c = t; c < 3*DHv; c += 256) {
            float acc = 0.f;
            #pragma unroll 16
            for (int k = 0; k < DNv; k++) acc += sx[k] * __ldg(&Wqn[k*384 + c]);
            g_qkvn[row*384 + c] = acc;
        }
    }
}

// ---------------- fused edge update kernel -----------------------------------
// block = (b, i, j-tile of 32), 256 threads.  r2 aliases stT (disjoint lifetimes)
#define SMEM_EDGE ((128*36 + 256*36 + 2048 + 64*36 + 256) * 4)
__global__ void __launch_bounds__(256, 3) k_edge(
                       const float* __restrict__ We0, const float* __restrict__ be0,
                       const float* __restrict__ We1, const float* __restrict__ be1,
                       const float* __restrict__ g0, const float* __restrict__ b0,
                       const float* __restrict__ Wem1, const float* __restrict__ Wem2,
                       const float* __restrict__ bem2,
                       const float* __restrict__ g1, const float* __restrict__ b1,
                       const float* __restrict__ eread, float* __restrict__ ewrite) {
    extern __shared__ float sm[];
    float* secatT = sm;                 // [k=128][jj=32] stride 36
    float* shT    = secatT + 128*36;    // [k=256][jj=32] stride 36
    float* stRM   = shT + 256*36;       // [jj=32][c=64] row-major
    float* stT    = stRM + 2048;        // [k=64][jj=32] stride 36
    float* r2     = stT;                // ALIAS: r2 live only after stT is dead
    float* ssrc   = stT + 64*36;        // 256

    int jt = blockIdx.x & 7;
    int bi = blockIdx.x >> 3;           // b*N+i
    int b = bi >> 8, i = bi & 255;
    int j0 = jt * 32;
    int t = threadIdx.x;

    // load ecat = [e_ij, e_ji] transposed
    for (int idx = t; idx < 32*64; idx += 256) {
        int jj = idx >> 6, c = idx & 63;
        secatT[c*36 + jj]        = eread[((size_t)bi*NNODE + j0 + jj)*DEv + c];
        secatT[(64 + c)*36 + jj] = eread[((size_t)(b*NNODE + j0 + jj)*NNODE + i)*DEv + c];
    }
    ssrc[t] = g_src[(size_t)bi*DEHv + t];
    __syncthreads();

    // h = gelu(ecat @ We0 + be0 + src_i + tgt_j)   (32 x 256), C=2 cols x 16 rows
    {
        int c = t & 127;     // cols c and c+128
        int jg = t >> 7;     // row-half: rows jg*16 .. jg*16+15
        u64t acc0[8], acc1[8];
        u64t init0 = pack_ww(__ldg(&be0[c])       + ssrc[c]);
        u64t init1 = pack_ww(__ldg(&be0[c + 128]) + ssrc[c + 128]);
        #pragma unroll
        for (int q = 0; q < 8; q++) { acc0[q] = init0; acc1[q] = init1; }
        #pragma unroll 4
        for (int k = 0; k < 128; k++) {
            u64t w0 = pack_ww(__ldg(&We0[k*DEHv + c]));
            u64t w1 = pack_ww(__ldg(&We0[k*DEHv + c + 128]));
            const float4* e4 = (const float4*)(secatT + k*36 + jg*16);
            #pragma unroll
            for (int q4 = 0; q4 < 4; q4++) {
                F4u ev; ev.v = e4[q4];
                ffma2(acc0[q4*2],   ev.p[0], w0);
                ffma2(acc0[q4*2+1], ev.p[1], w0);
                ffma2(acc1[q4*2],   ev.p[0], w1);
                ffma2(acc1[q4*2+1], ev.p[1], w1);
            }
        }
        #pragma unroll
        for (int q = 0; q < 8; q++) {
            int jj = jg*16 + 2*q;
            size_t tb0 = (size_t)(b*NNODE + j0 + jj)*DEHv;
            size_t tb1 = (size_t)(b*NNODE + j0 + jj + 1)*DEHv;
            U2u u0; u0.p = acc0[q];
            shT[c*36 + jj]     = gelu_f(u0.f[0] + __ldg(&g_tgt[tb0 + c]));
            shT[c*36 + jj + 1] = gelu_f(u0.f[1] + __ldg(&g_tgt[tb1 + c]));
            U2u u1; u1.p = acc1[q];
            shT[(c+128)*36 + jj]     = gelu_f(u1.f[0] + __ldg(&g_tgt[tb0 + c + 128]));
            shT[(c+128)*36 + jj + 1] = gelu_f(u1.f[1] + __ldg(&g_tgt[tb1 + c + 128]));
        }
    }
    __syncthreads();

    // e_pre = e + h @ We1 + be1  (32 x 64), K-split 2 x row-split 2 (R=16)
    {
        int c = t & 63, g = t >> 6;
        int rh = g & 1, kg = g >> 1;
        u64t acc[8];
        #pragma unroll
        for (int n = 0; n < 8; n++) acc[n] = 0ull;
        int kbeg = kg*128;
        #pragma unroll 8
        for (int kk = 0; kk < 128; kk++) {
            int k = kbeg + kk;
            u64t ww = pack_ww(__ldg(&We1[k*64 + c]));
            const float4* h4 = (const float4*)(shT + k*36 + rh*16);
            F4u a0, a1, a2, a3; a0.v = h4[0]; a1.v = h4[1]; a2.v = h4[2]; a3.v = h4[3];
            ffma2(acc[0], a0.p[0], ww); ffma2(acc[1], a0.p[1], ww);
            ffma2(acc[2], a1.p[0], ww); ffma2(acc[3], a1.p[1], ww);
            ffma2(acc[4], a2.p[0], ww); ffma2(acc[5], a2.p[1], ww);
            ffma2(acc[6], a3.p[0], ww); ffma2(acc[7], a3.p[1], ww);
        }
        u64t* scr = (u64t*)stT;  // stT not yet written; free as scratch
        if (kg == 1) {
            #pragma unroll
            for (int n = 0; n < 8; n++) scr[(n*2 + rh)*64 + c] = acc[n];
        }
        __syncthreads();
        if (kg == 0) {
            float bb1 = __ldg(&be1[c]);
            #pragma unroll
            for (int n = 0; n < 8; n++) {
                U2u u; u.p = acc[n];
                U2u v; v.p = scr[(n*2 + rh)*64 + c];
                int jj = rh*16 + 2*n;
                stRM[jj*64 + c]     = u.f[0] + v.f[0] + bb1 + eread[((size_t)bi*NNODE + j0 + jj)*DEv + c];
                stRM[(jj+1)*64 + c] = u.f[1] + v.f[1] + bb1 + eread[((size_t)bi*NNODE + j0 + jj + 1)*DEv + c];
            }
        }
    }
    __syncthreads();

    // LN0 per 64-wide row -> stRM (normalized) and stT (transposed)
    {
        int warp = t >> 5, lane = t & 31;
        for (int r = warp; r < 32; r += 8) {
            float a = stRM[r*64 + lane], q = stRM[r*64 + 32 + lane];
            float s = a + q, ss = a*a + q*q;
            #pragma unroll
            for (int off = 16; off; off >>= 1) {
                s  += __shfl_xor_sync(0xffffffffu, s, off);
                ss += __shfl_xor_sync(0xffffffffu, ss, off);
            }
            float mean = s * (1.f/64.f);
            float var = ss * (1.f/64.f) - mean*mean;
            float rstd = rsqrtf(var + 1e-5f);
            float y0 = (a - mean)*rstd*__ldg(&g0[lane])      + __ldg(&b0[lane]);
            float y1 = (q - mean)*rstd*__ldg(&g0[lane + 32]) + __ldg(&b0[lane + 32]);
            stRM[r*64 + lane] = y0; stRM[r*64 + 32 + lane] = y1;
            stT[lane*36 + r] = y0; stT[(lane + 32)*36 + r] = y1;
        }
    }
    __syncthreads();

    // hidden2 = gelu(e_new @ Wem1)   (32 x 256), reuse shT; C=2 cols x 16 rows
    {
        int c = t & 127;
        int jg = t >> 7;
        u64t acc0[8], acc1[8];
        #pragma unroll
        for (int q = 0; q < 8; q++) { acc0[q] = 0ull; acc1[q] = 0ull; }
        #pragma unroll 4
        for (int k = 0; k < 64; k++) {
            u64t w0 = pack_ww(__ldg(&Wem1[k*DEHv + c]));
            u64t w1 = pack_ww(__ldg(&Wem1[k*DEHv + c + 128]));
            const float4* e4 = (const float4*)(stT + k*36 + jg*16);
            #pragma unroll
            for (int q4 = 0; q4 < 4; q4++) {
                F4u ev; ev.v = e4[q4];
                ffma2(acc0[q4*2],   ev.p[0], w0);
                ffma2(acc0[q4*2+1], ev.p[1], w0);
                ffma2(acc1[q4*2],   ev.p[0], w1);
                ffma2(acc1[q4*2+1], ev.p[1], w1);
            }
        }
        #pragma unroll
        for (int q = 0; q < 8; q++) {
            int jj = jg*16 + 2*q;
            U2u u0; u0.p = acc0[q];
            shT[c*36 + jj]     = gelu_f(u0.f[0]);
            shT[c*36 + jj + 1] = gelu_f(u0.f[1]);
            U2u u1; u1.p = acc1[q];
            shT[(c+128)*36 + jj]     = gelu_f(u1.f[0]);
            shT[(c+128)*36 + jj + 1] = gelu_f(u1.f[1]);
        }
    }
    __syncthreads();

    // r2 = e_new + hidden2 @ Wem2 + bem2  (32 x 64), K-split 2 x row-split 2
    {
        int c = t & 63, g = t >> 6;
        int rh = g & 1, kg = g >> 1;
        u64t acc[8];
        #pragma unroll
        for (int n = 0; n < 8; n++) acc[n] = 0ull;
        int kbeg = kg*128;
        #pragma unroll 8
        for (int kk = 0; kk < 128; kk++) {
            int k = kbeg + kk;
            u64t ww = pack_ww(__ldg(&Wem2[k*64 + c]));
            const float4* h4 = (const float4*)(shT + k*36 + rh*16);
            F4u a0, a1, a2, a3; a0.v = h4[0]; a1.v = h4[1]; a2.v = h4[2]; a3.v = h4[3];
            ffma2(acc[0], a0.p[0], ww); ffma2(acc[1], a0.p[1], ww);
            ffma2(acc[2], a1.p[0], ww); ffma2(acc[3], a1.p[1], ww);
            ffma2(acc[4], a2.p[0], ww); ffma2(acc[5], a2.p[1], ww);
            ffma2(acc[6], a3.p[0], ww); ffma2(acc[7], a3.p[1], ww);
        }
        u64t* scr = (u64t*)secatT;  // secatT free at this stage
        if (kg == 1) {
            #pragma unroll
            for (int n = 0; n < 8; n++) scr[(n*2 + rh)*64 + c] = acc[n];
        }
        __syncthreads();
        if (kg == 0) {
            float bb2 = __ldg(&bem2[c]);
            #pragma unroll
            for (int n = 0; n < 8; n++) {
                U2u u; u.p = acc[n];
                U2u v; v.p = scr[(n*2 + rh)*64 + c];
                int jj = rh*16 + 2*n;
                r2[jj*64 + c]     = u.f[0] + v.f[0] + bb2 + stRM[jj*64 + c];
                r2[(jj+1)*64 + c] = u.f[1] + v.f[1] + bb2 + stRM[(jj+1)*64 + c];
            }
        }
    }
    __syncthreads();

    // LN1 per row -> write out
    {
        int warp = t >> 5, lane = t & 31;
        for (int r = warp; r < 32; r += 8) {
            float a = r2[r*64 + lane], q = r2[r*64 + 32 + lane];
            float s = a + q, ss = a*a + q*q;
            #pragma unroll
            for (int off = 16; off; off >>= 1) {
                s  += __shfl_xor_sync(0xffffffffu, s, off);
                ss += __shfl_xor_sync(0xffffffffu, ss, off);
            }
            float mean = s * (1.f/64.f);
            float var = ss * (1.f/64.f) - mean*mean;
            float rstd = rsqrtf(var + 1e-5f);
            float y0 = (a - mean)*rstd*__ldg(&g1[lane])      + __ldg(&b1[lane]);
            float y1 = (q - mean)*rstd*__ldg(&g1[lane + 32]) + __ldg(&b1[lane + 32]);
            size_t orow = ((size_t)bi*NNODE + j0 + r)*DEv;
            ewrite[orow + lane] = y0;
            ewrite[orow + 32 + lane] = y1;
        }
    }
}

// ---------------- host launcher ----------------------------------------------
extern "C" void kernel_launch(void* const* d_in, const int* in_sizes, int n_in,
                              void* d_out, int out_size) {
    const float* node   = (const float*)d_in[0];
    const float* edge   = (const float*)d_in[1];
    const float* Wqkv_n = (const float*)d_in[2];
    const float* Wqkv_e = (const float*)d_in[3];
    const float* Wo     = (const float*)d_in[4];
    const float* bo     = (const float*)d_in[5];
    const float* Wl0    = (const float*)d_in[6];
    const float* bl0    = (const float*)d_in[7];
    const float* ln0_g  = (const float*)d_in[8];
    const float* ln0_b  = (const float*)d_in[9];
    const float* Wm1    = (const float*)d_in[10];
    const float* Wm2    = (const float*)d_in[11];
    const float* bm2    = (const float*)d_in[12];
    const float* ln1_g  = (const float*)d_in[13];
    const float* ln1_b  = (const float*)d_in[14];
    const float* We0    = (const float*)d_in[15];
    const float* be0    = (const float*)d_in[16];
    const float* Ws     = (const float*)d_in[17];
    const float* bs     = (const float*)d_in[18];
    const float* Wt     = (const float*)d_in[19];
    const float* bt     = (const float*)d_in[20];
    const float* We1    = (const float*)d_in[21];
    const float* be1    = (const float*)d_in[22];
    const float* eln0_g = (const float*)d_in[23];
    const float* eln0_b = (const float*)d_in[24];
    const float* Wem1   = (const float*)d_in[25];
    const float* Wem2   = (const float*)d_in[26];
    const float* bem2   = (const float*)d_in[27];
    const float* eln1_g = (const float*)d_in[28];
    const float* eln1_b = (const float*)d_in[29];
    float* out = (float*)d_out;

    cudaFuncSetAttribute(k_attn, cudaFuncAttributeMaxDynamicSharedMemorySize, SMEM_ATTN);
    cudaFuncSetAttribute(k_edge, cudaFuncAttributeMaxDynamicSharedMemorySize, SMEM_EDGE);

    float* ebuf = nullptr;
    cudaGetSymbolAddress((void**)&ebuf, g_ebuf);
    float* out_e = out + BB*NNODE*DNv;   // e region of d_out

    k_copy_in<<<64, 256>>>((const float4*)node);
    k_qkvn<<<BB*NNODE, 128>>>(Wqkv_n);  // layer 0 qkv

    for (int l = 0; l < NLAYER; l++) {
        int has_next = (l + 1 < NLAYER);
        int ln = has_next ? l + 1 : l;
        // e buffer chain: input edge -> g_ebuf -> d_out e-region
        const float* eread = (l == 0) ? edge : ebuf;
        float* ewrite = has_next ? ebuf : out_e;
        k_attn<<<BB*NNODE, 256, SMEM_ATTN>>>(Wqkv_e + (size_t)l*DEv*4*DHv, eread,
                                             Wo + (size_t)l*DHv*DNv, bo + l*DNv,
                                             Wl0 + (size_t)l*DNv*DNv, bl0 + l*DNv,
                                             ln0_g + l*DNv, ln0_b + l*DNv);
        k_node2<<<BB*NNODE, 128>>>(Wm1 + (size_t)l*DNv*DNHv, Wm2 + (size_t)l*DNHv*DNv,
                                   bm2 + l*DNv, ln1_g + l*DNv, ln1_b + l*DNv,
                                   out, has_next ? 0 : 1);
        k_aux<<<BB*NNODE*2, 256>>>(Ws + (size_t)l*DNv*DEHv, bs + l*DEHv,
                                   Wt + (size_t)l*DNv*DEHv, bt + l*DEHv,
                                   Wqkv_n + (size_t)ln*DNv*3*DHv, has_next);
        k_edge<<<BB*NNODE*8, 256, SMEM_EDGE>>>(
            We0 + (size_t)l*2*DEv*DEHv, be0 + l*DEHv,
            We1 + (size_t)l*DEHv*DEv,  be1 + l*DEv,
            eln0_g + l*DEv, eln0_b + l*DEv,
            Wem1 + (size_t)l*DEv*DEHv, Wem2 + (size_t)l*DEHv*DEv,
            bem2 + l*DEv, eln1_g + l*DEv, eln1_b + l*DEv,
            eread, ewrite);
    }
}

// round 16
// speedup vs baseline: 1.0649x; 1.0021x over previous
#include <cuda_runtime.h>
#include <math.h>

// dims
#define BB   2
#define NNODE 256
#define DNv  128
#define DEv  64
#define DHv  128
#define Hh   8
#define DHHv 16
#define DNHv 512
#define DEHv 256
#define NLAYER 2
#define ATT_SCALE 0.088388347648318447f  // 1/sqrt(128)

typedef unsigned long long u64t;

// packed fp32x2 FMA (Blackwell): one issue slot, two fp32 FMAs, exact .rn numerics
__device__ __forceinline__ void ffma2(u64t& acc, u64t a, u64t b) {
    asm("fma.rn.f32x2 %0, %1, %2, %0;" : "+l"(acc) : "l"(a), "l"(b));
}
__device__ __forceinline__ u64t pack_ww(float w) {
    u64t r; asm("mov.b64 %0, {%1, %1};" : "=l"(r) : "f"(w)); return r;
}
__device__ __forceinline__ u64t pack2(float a, float b) {
    u64t r; asm("mov.b64 %0, {%1, %2};" : "=l"(r) : "f"(a), "f"(b)); return r;
}
union F4u { float4 v; u64t p[2]; };
union U2u { u64t p; float f[2]; };

// ---------------- scratch (device globals; no allocations allowed) ----------
__device__ float g_x[BB*NNODE*DNv];
__device__ float g_ebuf[BB*NNODE*NNODE*DEv];   // intermediate e (after layer 0)
__device__ float g_qkvn[BB*NNODE*3*DHv];
__device__ float g_src[BB*NNODE*DEHv];
__device__ float g_tgt[BB*NNODE*DEHv];

__device__ __forceinline__ float gelu_f(float x) {
    return 0.5f * x * (1.0f + erff(x * 0.70710678118654752440f));
}

// ---------------- copy in: node features only --------------------------------
__global__ void k_copy_in(const float4* __restrict__ node) {
    int tid = blockIdx.x * blockDim.x + threadIdx.x;
    float4* x4 = (float4*)g_x;
    if (tid < BB*NNODE*DNv/4) x4[tid] = node[tid];
}

// ---------------- qkv_n for layer 0 only -------------------------------------
__global__ void k_qkvn(const float* __restrict__ W) {  // W: [128][384]
    __shared__ float sx[DNv];
    int row = blockIdx.x;
    int t = threadIdx.x;   // 128 threads
    sx[t] = g_x[row*DNv + t];
    __syncthreads();
    for (int c = t; c < 3*DHv; c += 128) {
        float acc = 0.f;
        #pragma unroll 16
        for (int k = 0; k < DNv; k++) acc += sx[k] * __ldg(&W[k*384 + c]);
        g_qkvn[row*384 + c] = acc;
    }
}

// ---------------- fused attention + node1: per (b,i) -------------------------
// R12 structure (occ 2, double-buffered seT prefetch) + fused node1 epilogue:
// x = ln(x + (attnout@Wo+bo)@Wl0 + bl0) computed in-block (row fully owned).
#define SE_STR 385
#define KV_STR 132
#define SET_HALF (64*36)
#define SMEM_ATTN ((32*SE_STR + 2*SET_HALF + 32*KV_STR + 32*KV_STR + 128 + 8*65 + 8*36) * 4)
__global__ void __launch_bounds__(256, 2) k_attn(const float* __restrict__ We,
                                                 const float* __restrict__ eread,
                                                 const float* __restrict__ Wo,
                                                 const float* __restrict__ bo,
                                                 const float* __restrict__ Wl0,
                                                 const float* __restrict__ bl0,
                                                 const float* __restrict__ g0,
                                                 const float* __restrict__ b0) {
    extern __shared__ float sm[];
    float* sE  = sm;                   // logical-col E tile, stride 385
    float* seT = sE  + 32*SE_STR;      // e tile transposed, DOUBLE buffer [2][64][36]
    float* skn = seT + 2*SET_HALF;     // kn tile [jj][128], stride 132
    float* svn = skn + 32*KV_STR;      // vn tile
    float* sq  = svn + 32*KV_STR;      // q row (128); later: attnout row
    float* sf  = sq + 128;             // f per head [8][65]; later: st[128]+sred
    float* sp  = sf + 8*65;            // p per head [8][36]

    int b = blockIdx.x / NNODE, i = blockIdx.x % NNODE;
    int t = threadIdx.x, warp = t >> 5, lane = t & 31;
    int h = warp;  // 8 warps = 8 heads
    int dd = lane & 15, hi = lane >> 4;  // AV split: lane half 'hi' owns j-rows hi*16..

    // E-GEMM worker mapping: rows rh*16..+15, logical cols cb, cb+128, cb+256
    int rh = t >> 7, cb = t & 127;
    int ac0, ac1, ac2;
    {
        int L0 = cb, L1 = cb + 128, L2 = cb + 256;
        int w0 = L0 % 48, w1 = L1 % 48, w2 = L2 % 48;
        ac0 = (L0/48)*64 + (w0 < 32 ? w0 : w0 + 16);
        ac1 = (L1/48)*64 + (w1 < 32 ? w1 : w1 + 16);
        ac2 = (L2/48)*64 + (w2 < 32 ? w2 : w2 + 16);
    }

    if (t < DHv) { int hh = t >> 4, d = t & 15; sq[t] = g_qkvn[(b*NNODE + i)*384 + hh*48 + d]; }

    float m = -3.4e38f, lsum = 0.f, o = 0.f;
    float f0 = 0.f, f1 = 0.f;           // f cols: lane, lane+32
    const float* erow = eread + (size_t)(b*NNODE + i) * NNODE * DEv;

    // preload tile 0 into seT buffer 0
    for (int idx = t; idx < 32*64; idx += 256) {
        int jj = idx >> 6, c = idx & 63;
        seT[c*36 + jj] = erow[jj*DEv + c];
    }
    int cur = 0;

    for (int j0 = 0; j0 < NNODE; j0 += 32) {
        float* seTc = seT + cur*SET_HALF;
        float* seTn = seT + (cur^1)*SET_HALF;
        __syncthreads();  // prev tile readers done; seTc (stored last iter) visible
        // load kn, vn tiles (float4: 32 rows x 8 heads x 4 f4-units)
        #pragma unroll
        for (int u = 0; u < 4; u++) {
            int idx = t + u*256;
            int jj = idx >> 5, uu = idx & 31;
            int hh = uu >> 2, q4u = uu & 3;
            const float4* src = (const float4*)(g_qkvn + (size_t)(b*NNODE + j0 + jj)*384 + hh*48 + 16);
            ((float4*)(skn + jj*KV_STR + hh*16))[q4u] = __ldg(&src[q4u]);
            ((float4*)(svn + jj*KV_STR + hh*16))[q4u] = __ldg(&src[4 + q4u]);
        }
        // issue prefetch LDGs for next e tile (consumed after the GEMM)
        float pf[8];
        int jn = j0 + 32;
        if (jn < NNODE) {
            #pragma unroll
            for (int u = 0; u < 8; u++) {
                int idx = t + u*256;
                int jj = idx >> 6, c = idx & 63;
                pf[u] = __ldg(&erow[(jn + jj)*DEv + c]);
            }
        }
        __syncthreads();  // skn/svn ready
        // E = e_tile @ Wqkv_e[eq,ek,em]  (32 x 384): all 256 threads, 3 cols x 16 rows
        {
            u64t a0[8], a1[8], a2[8];
            #pragma unroll
            for (int q = 0; q < 8; q++) { a0[q] = 0ull; a1[q] = 0ull; a2[q] = 0ull; }
            #pragma unroll 4
            for (int k = 0; k < 64; k++) {
                u64t w0 = pack_ww(__ldg(&We[k*512 + ac0]));
                u64t w1 = pack_ww(__ldg(&We[k*512 + ac1]));
                u64t w2 = pack_ww(__ldg(&We[k*512 + ac2]));
                const float4* e4 = (const float4*)(seTc + k*36 + rh*16);
                #pragma unroll
                for (int q4 = 0; q4 < 4; q4++) {
                    F4u ev; ev.v = e4[q4];
                    ffma2(a0[q4*2],   ev.p[0], w0);
                    ffma2(a0[q4*2+1], ev.p[1], w0);
                    ffma2(a1[q4*2],   ev.p[0], w1);
                    ffma2(a1[q4*2+1], ev.p[1], w1);
                    ffma2(a2[q4*2],   ev.p[0], w2);
                    ffma2(a2[q4*2+1], ev.p[1], w2);
                }
            }
            #pragma unroll
            for (int q = 0; q < 8; q++) {
                int row = rh*16 + 2*q;
                U2u u0; u0.p = a0[q];
                sE[row*SE_STR + cb]       = u0.f[0];
                sE[(row+1)*SE_STR + cb]   = u0.f[1];
                U2u u1; u1.p = a1[q];
                sE[row*SE_STR + cb+128]     = u1.f[0];
                sE[(row+1)*SE_STR + cb+128] = u1.f[1];
                U2u u2; u2.p = a2[q];
                sE[row*SE_STR + cb+256]     = u2.f[0];
                sE[(row+1)*SE_STR + cb+256] = u2.f[1];
            }
        }
        // store prefetched next e tile into the other buffer (LDG latency now hidden)
        if (jn < NNODE) {
            #pragma unroll
            for (int u = 0; u < 8; u++) {
                int idx = t + u*256;
                int jj = idx >> 6, c = idx & 63;
                seTn[c*36 + jj] = pf[u];
            }
        }
        __syncthreads();  // sE ready
        // dots (lane = j within tile), online softmax per warp/head
        const float* Er = sE + lane*SE_STR + h*48;
        const float* kr = skn + lane*KV_STR + h*16;
        float dot = 0.f;
        #pragma unroll
        for (int d = 0; d < 16; d++)
            dot += (sq[h*16 + d] + Er[d]) * (kr[d] + Er[16 + d]);
        dot *= ATT_SCALE;
        float mt = dot;
        #pragma unroll
        for (int off = 16; off; off >>= 1) mt = fmaxf(mt, __shfl_xor_sync(0xffffffffu, mt, off));
        float mnew = fmaxf(m, mt);
        float p = expf(dot - mnew);
        float corr = expf(m - mnew);   // first tile: exp(-huge) = 0
        float ps = p;
        #pragma unroll
        for (int off = 16; off; off >>= 1) ps += __shfl_xor_sync(0xffffffffu, ps, off);
        lsum = lsum * corr + ps;
        o *= corr; f0 *= corr; f1 *= corr;
        // stage p for this warp's tile (own row; syncwarp is enough)
        sp[h*36 + lane] = p;
        __syncwarp();
        // f accumulation, float4 over j (seTc rows are j-contiguous)
        {
            const float4* pv4 = (const float4*)(sp + h*36);
            const float4* e0v = (const float4*)(seTc + lane*36);
            const float4* e1v = (const float4*)(seTc + (lane + 32)*36);
            #pragma unroll
            for (int jq = 0; jq < 8; jq++) {
                float4 pv = pv4[jq];
                float4 a = e0v[jq], bq = e1v[jq];
                f0 += pv.x*a.x + pv.y*a.y + pv.z*a.z + pv.w*a.w;
                f1 += pv.x*bq.x + pv.y*bq.y + pv.z*bq.z + pv.w*bq.w;
            }
        }
        // o[d] += sum_j p_j * vn[j,d]*em[j,d] — j split by lane-half
        #pragma unroll
        for (int jj = 0; jj < 16; jj++) {
            int jjj = hi*16 + jj;
            float pj = __shfl_sync(0xffffffffu, p, jjj);
            const float* Ej = sE + jjj*SE_STR + h*48;
            o += pj * (svn[jjj*KV_STR + h*16 + dd] * Ej[32 + dd]);
        }
        m = mnew;
        cur ^= 1;
    }
    // combine the two j-halves of o
    float of = o + __shfl_xor_sync(0xffffffffu, o, 16);
    // stash f for this head, then apply Wev projection (exact linear reorder)
    sf[h*65 + lane] = f0;
    sf[h*65 + 32 + lane] = f1;
    __syncwarp();
    float aout = 0.f;
    if (lane < 16) {
        float fv = 0.f;
        #pragma unroll 8
        for (int c = 0; c < 64; c++)
            fv += sf[h*65 + c] * __ldg(&We[c*512 + h*64 + 32 + lane]);
        aout = (of + fv) / lsum;
    }
    __syncthreads();            // sf readers done; repurpose sq/sf
    if (lane < 16) sq[h*16 + lane] = aout;   // sq := attnout row (128)
    float* st   = sf;           // st[128]
    float* sred = sf + 128;     // sred[10]
    __syncthreads();
    // ---- fused node1: x = ln(x + (attnout@Wo+bo)@Wl0 + bl0) ----
    int row = b*NNODE + i;
    if (t < DNv) {
        float acc = bo[t];
        #pragma unroll 16
        for (int k = 0; k < DHv; k++) acc += sq[k] * __ldg(&Wo[k*DNv + t]);
        st[t] = acc;
    }
    __syncthreads();
    float r = 0.f;
    if (t < DNv) {
        float u = bl0[t];
        #pragma unroll 16
        for (int k = 0; k < DNv; k++) u += st[k] * __ldg(&Wl0[k*DNv + t]);
        r = g_x[row*DNv + t] + u;
        float s = r, ss = r*r;
        #pragma unroll
        for (int off = 16; off; off >>= 1) {
            s  += __shfl_xor_sync(0xffffffffu, s, off);
            ss += __shfl_xor_sync(0xffffffffu, ss, off);
        }
        if (lane == 0) { sred[warp] = s; sred[4 + warp] = ss; }
    }
    __syncthreads();
    if (t == 0) {
        float S = sred[0]+sred[1]+sred[2]+sred[3];
        float SS = sred[4]+sred[5]+sred[6]+sred[7];
        float mean = S * (1.f/128.f);
        float var = SS * (1.f/128.f) - mean*mean;
        sred[8] = mean;
        sred[9] = rsqrtf(var + 1e-5f);
    }
    __syncthreads();
    if (t < DNv)
        g_x[row*DNv + t] = (r - sred[8]) * sred[9] * __ldg(&g0[t]) + __ldg(&b0[t]);
}

// ---------------- node MLP (256 threads): x = ln(x + gelu(x@Wm1)@Wm2 + bm2) --
// GEMM1: adjacent column pair per thread via LDG.64 + ffma2.
// GEMM2: k-split 2 across thread halves, smem combine. LN on threads 0..127.
__global__ void k_node2(const float* __restrict__ Wm1, const float* __restrict__ Wm2,
                        const float* __restrict__ bm2,
                        const float* __restrict__ gam, const float* __restrict__ bet,
                        float* __restrict__ xout, int wout) {
    __shared__ float sx[DNv];
    __shared__ float sh[DNHv];
    __shared__ float spart[DNv];
    __shared__ float sred[10];
    int row = blockIdx.x; int t = threadIdx.x;  // 256 threads
    int warp = t >> 5, lane = t & 31;
    if (t < DNv) sx[t] = g_x[row*DNv + t];
    __syncthreads();
    // GEMM1: cols (2t, 2t+1), packed
    {
        int c = 2*t;
        u64t acc = 0ull;
        #pragma unroll 16
        for (int k = 0; k < DNv; k++) {
            float2 w = __ldg((const float2*)&Wm1[k*DNHv + c]);
            ffma2(acc, pack_ww(sx[k]), pack2(w.x, w.y));
        }
        U2u u; u.p = acc;
        sh[c]     = gelu_f(u.f[0]);
        sh[c + 1] = gelu_f(u.f[1]);
    }
    __syncthreads();
    // GEMM2: output col = t&127, k-half = t>>7
    int c = t & 127, kg = t >> 7;
    float acc2 = 0.f;
    {
        int kb = kg*256;
        #pragma unroll 16
        for (int kk = 0; kk < 256; kk++)
            acc2 += sh[kb + kk] * __ldg(&Wm2[(kb + kk)*DNv + c]);
    }
    if (kg == 1) spart[c] = acc2;
    __syncthreads();
    float r = 0.f;
    if (kg == 0) {  // t < 128
        r = sx[c] + acc2 + spart[c] + bm2[c];
        float s = r, ss = r*r;
        #pragma unroll
        for (int off = 16; off; off >>= 1) {
            s  += __shfl_xor_sync(0xffffffffu, s, off);
            ss += __shfl_xor_sync(0xffffffffu, ss, off);
        }
        if (lane == 0) { sred[warp] = s; sred[4 + warp] = ss; }
    }
    __syncthreads();
    if (t == 0) {
        float S = sred[0]+sred[1]+sred[2]+sred[3];
        float SS = sred[4]+sred[5]+sred[6]+sred[7];
        float mean = S * (1.f/128.f);
        float var = SS * (1.f/128.f) - mean*mean;
        sred[8] = mean;
        sred[9] = rsqrtf(var + 1e-5f);
    }
    __syncthreads();
    if (kg == 0) {
        float y = (r - sred[8]) * sred[9] * gam[c] + bet[c];
        g_x[row*DNv + c] = y;
        if (wout) xout[row*DNv + c] = y;
    }
}

// ---------------- aux: srctgt (blocks 0..511) + next-layer qkvn (512..1023) --
__global__ void k_aux(const float* __restrict__ Ws, const float* __restrict__ bs,
                      const float* __restrict__ Wt, const float* __restrict__ bt,
                      const float* __restrict__ Wqn, int do_qkv) {
    __shared__ float sx[DNv];
    int t = threadIdx.x;  // 256 threads
    if (blockIdx.x < BB*NNODE) {
        int row = blockIdx.x;
        if (t < DNv) sx[t] = g_x[row*DNv + t];
        __syncthreads();
        float a = bs[t], c2 = bt[t];
        #pragma unroll 16
        for (int k = 0; k < DNv; k++) {
            float xv = sx[k];
            a  += xv * __ldg(&Ws[k*DEHv + t]);
            c2 += xv * __ldg(&Wt[k*DEHv + t]);
        }
        g_src[row*DEHv + t] = a;
        g_tgt[row*DEHv + t] = c2;
    } else {
        if (!do_qkv) return;
        int row = blockIdx.x - BB*NNODE;
        if (t < DNv) sx[t] = g_x[row*DNv + t];
        __syncthreads();
        for (int c = t; c < 3*DHv; c += 256) {
            float acc = 0.f;
            #pragma unroll 16
            for (int k = 0; k < DNv; k++) acc += sx[k] * __ldg(&Wqn[k*384 + c]);
            g_qkvn[row*384 + c] = acc;
        }
    }
}

// ---------------- fused edge update kernel -----------------------------------
// block = (b, i, j-tile of 32), 256 threads.  r2 aliases stT (disjoint lifetimes)
#define SMEM_EDGE ((128*36 + 256*36 + 2048 + 64*36 + 256) * 4)
__global__ void __launch_bounds__(256, 3) k_edge(
                       const float* __restrict__ We0, const float* __restrict__ be0,
                       const float* __restrict__ We1, const float* __restrict__ be1,
                       const float* __restrict__ g0, const float* __restrict__ b0,
                       const float* __restrict__ Wem1, const float* __restrict__ Wem2,
                       const float* __restrict__ bem2,
                       const float* __restrict__ g1, const float* __restrict__ b1,
                       const float* __restrict__ eread, float* __restrict__ ewrite) {
    extern __shared__ float sm[];
    float* secatT = sm;                 // [k=128][jj=32] stride 36
    float* shT    = secatT + 128*36;    // [k=256][jj=32] stride 36
    float* stRM   = shT + 256*36;       // [jj=32][c=64] row-major
    float* stT    = stRM + 2048;        // [k=64][jj=32] stride 36
    float* r2     = stT;                // ALIAS: r2 live only after stT is dead
    float* ssrc   = stT + 64*36;        // 256

    int jt = blockIdx.x & 7;
    int bi = blockIdx.x >> 3;           // b*N+i
    int b = bi >> 8, i = bi & 255;
    int j0 = jt * 32;
    int t = threadIdx.x;

    // load ecat = [e_ij, e_ji] transposed
    for (int idx = t; idx < 32*64; idx += 256) {
        int jj = idx >> 6, c = idx & 63;
        secatT[c*36 + jj]        = eread[((size_t)bi*NNODE + j0 + jj)*DEv + c];
        secatT[(64 + c)*36 + jj] = eread[((size_t)(b*NNODE + j0 + jj)*NNODE + i)*DEv + c];
    }
    ssrc[t] = g_src[(size_t)bi*DEHv + t];
    __syncthreads();

    // h = gelu(ecat @ We0 + be0 + src_i + tgt_j)   (32 x 256), C=2 cols x 16 rows
    {
        int c = t & 127;     // cols c and c+128
        int jg = t >> 7;     // row-half: rows jg*16 .. jg*16+15
        u64t acc0[8], acc1[8];
        u64t init0 = pack_ww(__ldg(&be0[c])       + ssrc[c]);
        u64t init1 = pack_ww(__ldg(&be0[c + 128]) + ssrc[c + 128]);
        #pragma unroll
        for (int q = 0; q < 8; q++) { acc0[q] = init0; acc1[q] = init1; }
        #pragma unroll 4
        for (int k = 0; k < 128; k++) {
            u64t w0 = pack_ww(__ldg(&We0[k*DEHv + c]));
            u64t w1 = pack_ww(__ldg(&We0[k*DEHv + c + 128]));
            const float4* e4 = (const float4*)(secatT + k*36 + jg*16);
            #pragma unroll
            for (int q4 = 0; q4 < 4; q4++) {
                F4u ev; ev.v = e4[q4];
                ffma2(acc0[q4*2],   ev.p[0], w0);
                ffma2(acc0[q4*2+1], ev.p[1], w0);
                ffma2(acc1[q4*2],   ev.p[0], w1);
                ffma2(acc1[q4*2+1], ev.p[1], w1);
            }
        }
        #pragma unroll
        for (int q = 0; q < 8; q++) {
            int jj = jg*16 + 2*q;
            size_t tb0 = (size_t)(b*NNODE + j0 + jj)*DEHv;
            size_t tb1 = (size_t)(b*NNODE + j0 + jj + 1)*DEHv;
            U2u u0; u0.p = acc0[q];
            shT[c*36 + jj]     = gelu_f(u0.f[0] + __ldg(&g_tgt[tb0 + c]));
            shT[c*36 + jj + 1] = gelu_f(u0.f[1] + __ldg(&g_tgt[tb1 + c]));
            U2u u1; u1.p = acc1[q];
            shT[(c+128)*36 + jj]     = gelu_f(u1.f[0] + __ldg(&g_tgt[tb0 + c + 128]));
            shT[(c+128)*36 + jj + 1] = gelu_f(u1.f[1] + __ldg(&g_tgt[tb1 + c + 128]));
        }
    }
    __syncthreads();

    // e_pre = e + h @ We1 + be1  (32 x 64), K-split 2 x row-split 2 (R=16)
    {
        int c = t & 63, g = t >> 6;
        int rh = g & 1, kg = g >> 1;
        u64t acc[8];
        #pragma unroll
        for (int n = 0; n < 8; n++) acc[n] = 0ull;
        int kbeg = kg*128;
        #pragma unroll 8
        for (int kk = 0; kk < 128; kk++) {
            int k = kbeg + kk;
            u64t ww = pack_ww(__ldg(&We1[k*64 + c]));
            const float4* h4 = (const float4*)(shT + k*36 + rh*16);
            F4u a0, a1, a2, a3; a0.v = h4[0]; a1.v = h4[1]; a2.v = h4[2]; a3.v = h4[3];
            ffma2(acc[0], a0.p[0], ww); ffma2(acc[1], a0.p[1], ww);
            ffma2(acc[2], a1.p[0], ww); ffma2(acc[3], a1.p[1], ww);
            ffma2(acc[4], a2.p[0], ww); ffma2(acc[5], a2.p[1], ww);
            ffma2(acc[6], a3.p[0], ww); ffma2(acc[7], a3.p[1], ww);
        }
        u64t* scr = (u64t*)stT;  // stT not yet written; free as scratch
        if (kg == 1) {
            #pragma unroll
            for (int n = 0; n < 8; n++) scr[(n*2 + rh)*64 + c] = acc[n];
        }
        __syncthreads();
        if (kg == 0) {
            float bb1 = __ldg(&be1[c]);
            #pragma unroll
            for (int n = 0; n < 8; n++) {
                U2u u; u.p = acc[n];
                U2u v; v.p = scr[(n*2 + rh)*64 + c];
                int jj = rh*16 + 2*n;
                stRM[jj*64 + c]     = u.f[0] + v.f[0] + bb1 + eread[((size_t)bi*NNODE + j0 + jj)*DEv + c];
                stRM[(jj+1)*64 + c] = u.f[1] + v.f[1] + bb1 + eread[((size_t)bi*NNODE + j0 + jj + 1)*DEv + c];
            }
        }
    }
    __syncthreads();

    // LN0 per 64-wide row -> stRM (normalized) and stT (transposed)
    {
        int warp = t >> 5, lane = t & 31;
        for (int r = warp; r < 32; r += 8) {
            float a = stRM[r*64 + lane], q = stRM[r*64 + 32 + lane];
            float s = a + q, ss = a*a + q*q;
            #pragma unroll
            for (int off = 16; off; off >>= 1) {
                s  += __shfl_xor_sync(0xffffffffu, s, off);
                ss += __shfl_xor_sync(0xffffffffu, ss, off);
            }
            float mean = s * (1.f/64.f);
            float var = ss * (1.f/64.f) - mean*mean;
            float rstd = rsqrtf(var + 1e-5f);
            float y0 = (a - mean)*rstd*__ldg(&g0[lane])      + __ldg(&b0[lane]);
            float y1 = (q - mean)*rstd*__ldg(&g0[lane + 32]) + __ldg(&b0[lane + 32]);
            stRM[r*64 + lane] = y0; stRM[r*64 + 32 + lane] = y1;
            stT[lane*36 + r] = y0; stT[(lane + 32)*36 + r] = y1;
        }
    }
    __syncthreads();

    // hidden2 = gelu(e_new @ Wem1)   (32 x 256), reuse shT; C=2 cols x 16 rows
    {
        int c = t & 127;
        int jg = t >> 7;
        u64t acc0[8], acc1[8];
        #pragma unroll
        for (int q = 0; q < 8; q++) { acc0[q] = 0ull; acc1[q] = 0ull; }
        #pragma unroll 4
        for (int k = 0; k < 64; k++) {
            u64t w0 = pack_ww(__ldg(&Wem1[k*DEHv + c]));
            u64t w1 = pack_ww(__ldg(&Wem1[k*DEHv + c + 128]));
            const float4* e4 = (const float4*)(stT + k*36 + jg*16);
            #pragma unroll
            for (int q4 = 0; q4 < 4; q4++) {
                F4u ev; ev.v = e4[q4];
                ffma2(acc0[q4*2],   ev.p[0], w0);
                ffma2(acc0[q4*2+1], ev.p[1], w0);
                ffma2(acc1[q4*2],   ev.p[0], w1);
                ffma2(acc1[q4*2+1], ev.p[1], w1);
            }
        }
        #pragma unroll
        for (int q = 0; q < 8; q++) {
            int jj = jg*16 + 2*q;
            U2u u0; u0.p = acc0[q];
            shT[c*36 + jj]     = gelu_f(u0.f[0]);
            shT[c*36 + jj + 1] = gelu_f(u0.f[1]);
            U2u u1; u1.p = acc1[q];
            shT[(c+128)*36 + jj]     = gelu_f(u1.f[0]);
            shT[(c+128)*36 + jj + 1] = gelu_f(u1.f[1]);
        }
    }
    __syncthreads();

    // r2 = e_new + hidden2 @ Wem2 + bem2  (32 x 64), K-split 2 x row-split 2
    {
        int c = t & 63, g = t >> 6;
        int rh = g & 1, kg = g >> 1;
        u64t acc[8];
        #pragma unroll
        for (int n = 0; n < 8; n++) acc[n] = 0ull;
        int kbeg = kg*128;
        #pragma unroll 8
        for (int kk = 0; kk < 128; kk++) {
            int k = kbeg + kk;
            u64t ww = pack_ww(__ldg(&Wem2[k*64 + c]));
            const float4* h4 = (const float4*)(shT + k*36 + rh*16);
            F4u a0, a1, a2, a3; a0.v = h4[0]; a1.v = h4[1]; a2.v = h4[2]; a3.v = h4[3];
            ffma2(acc[0], a0.p[0], ww); ffma2(acc[1], a0.p[1], ww);
            ffma2(acc[2], a1.p[0], ww); ffma2(acc[3], a1.p[1], ww);
            ffma2(acc[4], a2.p[0], ww); ffma2(acc[5], a2.p[1], ww);
            ffma2(acc[6], a3.p[0], ww); ffma2(acc[7], a3.p[1], ww);
        }
        u64t* scr = (u64t*)secatT;  // secatT free at this stage
        if (kg == 1) {
            #pragma unroll
            for (int n = 0; n < 8; n++) scr[(n*2 + rh)*64 + c] = acc[n];
        }
        __syncthreads();
        if (kg == 0) {
            float bb2 = __ldg(&bem2[c]);
            #pragma unroll
            for (int n = 0; n < 8; n++) {
                U2u u; u.p = acc[n];
                U2u v; v.p = scr[(n*2 + rh)*64 + c];
                int jj = rh*16 + 2*n;
                r2[jj*64 + c]     = u.f[0] + v.f[0] + bb2 + stRM[jj*64 + c];
                r2[(jj+1)*64 + c] = u.f[1] + v.f[1] + bb2 + stRM[(jj+1)*64 + c];
            }
        }
    }
    __syncthreads();

    // LN1 per row -> write out
    {
        int warp = t >> 5, lane = t & 31;
        for (int r = warp; r < 32; r += 8) {
            float a = r2[r*64 + lane], q = r2[r*64 + 32 + lane];
            float s = a + q, ss = a*a + q*q;
            #pragma unroll
            for (int off = 16; off; off >>= 1) {
                s  += __shfl_xor_sync(0xffffffffu, s, off);
                ss += __shfl_xor_sync(0xffffffffu, ss, off);
            }
            float mean = s * (1.f/64.f);
            float var = ss * (1.f/64.f) - mean*mean;
            float rstd = rsqrtf(var + 1e-5f);
            float y0 = (a - mean)*rstd*__ldg(&g1[lane])      + __ldg(&b1[lane]);
            float y1 = (q - mean)*rstd*__ldg(&g1[lane + 32]) + __ldg(&b1[lane + 32]);
            size_t orow = ((size_t)bi*NNODE + j0 + r)*DEv;
            ewrite[orow + lane] = y0;
            ewrite[orow + 32 + lane] = y1;
        }
    }
}

// ---------------- host launcher ----------------------------------------------
extern "C" void kernel_launch(void* const* d_in, const int* in_sizes, int n_in,
                              void* d_out, int out_size) {
    const float* node   = (const float*)d_in[0];
    const float* edge   = (const float*)d_in[1];
    const float* Wqkv_n = (const float*)d_in[2];
    const float* Wqkv_e = (const float*)d_in[3];
    const float* Wo     = (const float*)d_in[4];
    const float* bo     = (const float*)d_in[5];
    const float* Wl0    = (const float*)d_in[6];
    const float* bl0    = (const float*)d_in[7];
    const float* ln0_g  = (const float*)d_in[8];
    const float* ln0_b  = (const float*)d_in[9];
    const float* Wm1    = (const float*)d_in[10];
    const float* Wm2    = (const float*)d_in[11];
    const float* bm2    = (const float*)d_in[12];
    const float* ln1_g  = (const float*)d_in[13];
    const float* ln1_b  = (const float*)d_in[14];
    const float* We0    = (const float*)d_in[15];
    const float* be0    = (const float*)d_in[16];
    const float* Ws     = (const float*)d_in[17];
    const float* bs     = (const float*)d_in[18];
    const float* Wt     = (const float*)d_in[19];
    const float* bt     = (const float*)d_in[20];
    const float* We1    = (const float*)d_in[21];
    const float* be1    = (const float*)d_in[22];
    const float* eln0_g = (const float*)d_in[23];
    const float* eln0_b = (const float*)d_in[24];
    const float* Wem1   = (const float*)d_in[25];
    const float* Wem2   = (const float*)d_in[26];
    const float* bem2   = (const float*)d_in[27];
    const float* eln1_g = (const float*)d_in[28];
    const float* eln1_b = (const float*)d_in[29];
    float* out = (float*)d_out;

    cudaFuncSetAttribute(k_attn, cudaFuncAttributeMaxDynamicSharedMemorySize, SMEM_ATTN);
    cudaFuncSetAttribute(k_edge, cudaFuncAttributeMaxDynamicSharedMemorySize, SMEM_EDGE);

    float* ebuf = nullptr;
    cudaGetSymbolAddress((void**)&ebuf, g_ebuf);
    float* out_e = out + BB*NNODE*DNv;   // e region of d_out

    k_copy_in<<<64, 256>>>((const float4*)node);
    k_qkvn<<<BB*NNODE, 128>>>(Wqkv_n);  // layer 0 qkv

    for (int l = 0; l < NLAYER; l++) {
        int has_next = (l + 1 < NLAYER);
        int ln = has_next ? l + 1 : l;
        // e buffer chain: input edge -> g_ebuf -> d_out e-region
        const float* eread = (l == 0) ? edge : ebuf;
        float* ewrite = has_next ? ebuf : out_e;
        k_attn<<<BB*NNODE, 256, SMEM_ATTN>>>(Wqkv_e + (size_t)l*DEv*4*DHv, eread,
                                             Wo + (size_t)l*DHv*DNv, bo + l*DNv,
                                             Wl0 + (size_t)l*DNv*DNv, bl0 + l*DNv,
                                             ln0_g + l*DNv, ln0_b + l*DNv);
        k_node2<<<BB*NNODE, 256>>>(Wm1 + (size_t)l*DNv*DNHv, Wm2 + (size_t)l*DNHv*DNv,
                                   bm2 + l*DNv, ln1_g + l*DNv, ln1_b + l*DNv,
                                   out, has_next ? 0 : 1);
        k_aux<<<BB*NNODE*2, 256>>>(Ws + (size_t)l*DNv*DEHv, bs + l*DEHv,
                                   Wt + (size_t)l*DNv*DEHv, bt + l*DEHv,
                                   Wqkv_n + (size_t)ln*DNv*3*DHv, has_next);
        k_edge<<<BB*NNODE*8, 256, SMEM_EDGE>>>(
            We0 + (size_t)l*2*DEv*DEHv, be0 + l*DEHv,
            We1 + (size_t)l*DEHv*DEv,  be1 + l*DEv,
            eln0_g + l*DEv, eln0_b + l*DEv,
            Wem1 + (size_t)l*DEv*DEHv, Wem2 + (size_t)l*DEHv*DEv,
            bem2 + l*DEv, eln1_g + l*DEv, eln1_b + l*DEv,
            eread, ewrite);
    }
}